// round 4
// baseline (speedup 1.0000x reference)
#include <cuda_runtime.h>
#include <cuda_bf16.h>
#include <math.h>

// Problem constants
#define NPIX   131072      // B*H*W = 8*128*128
#define BATCH  8
#define HH     128
#define WW     128
#define CDIM   192
#define C3     576         // 3*CDIM
#define HEADS  6
#define HD     32          // head dim
#define HID    510
#define HID2   1020        // 2*HID
#define UGLD   512         // padded lda for gated ffn activation (cols 510,511 zeroed)
#define NPB    16384       // pixels per batch

// ---------------- scratch (device globals; allocation-free rule) ----------------
__device__ float g_y[(size_t)NPIX * CDIM];
__device__ float g_qkv_pre[(size_t)NPIX * C3];
__device__ float g_qkv[(size_t)NPIX * C3];
__device__ float g_part[48 * 16 * 1024];     // partial K^T Q sums, 16 chunks
__device__ float g_attn[48 * 1024];
__device__ float g_W2[BATCH * CDIM * CDIM];  // attn folded into w_proj, per batch
__device__ float g_x1[(size_t)NPIX * CDIM];
__device__ float g_upre[(size_t)NPIX * HID2];
__device__ float g_ug[(size_t)NPIX * UGLD];

// ---------------- mma / ldmatrix helpers ----------------
__device__ __forceinline__ void ldsm4(unsigned* r, unsigned addr) {
    asm volatile("ldmatrix.sync.aligned.m8n8.x4.shared.b16 {%0,%1,%2,%3}, [%4];"
                 : "=r"(r[0]), "=r"(r[1]), "=r"(r[2]), "=r"(r[3]) : "r"(addr));
}
__device__ __forceinline__ void ldsm4t(unsigned* r, unsigned addr) {
    asm volatile("ldmatrix.sync.aligned.m8n8.x4.trans.shared.b16 {%0,%1,%2,%3}, [%4];"
                 : "=r"(r[0]), "=r"(r[1]), "=r"(r[2]), "=r"(r[3]) : "r"(addr));
}
__device__ __forceinline__ void mma_bf16(float* d, const unsigned* a, unsigned b0, unsigned b1) {
    asm volatile(
        "mma.sync.aligned.m16n8k16.row.col.f32.bf16.bf16.f32 "
        "{%0,%1,%2,%3},{%4,%5,%6,%7},{%8,%9},{%0,%1,%2,%3};"
        : "+f"(d[0]), "+f"(d[1]), "+f"(d[2]), "+f"(d[3])
        : "r"(a[0]), "r"(a[1]), "r"(a[2]), "r"(a[3]), "r"(b0), "r"(b1));
}

// ---------------- LayerNorm (one warp per pixel, C=192 = 6 per lane) ----------------
__global__ void ln_kernel(const float* __restrict__ x, const float* __restrict__ g,
                          const float* __restrict__ b, float* __restrict__ y) {
    size_t warp = ((size_t)blockIdx.x * blockDim.x + threadIdx.x) >> 5;
    int lane = threadIdx.x & 31;
    const float* xr = x + warp * CDIM;
    float v[6]; float s = 0.f, s2 = 0.f;
#pragma unroll
    for (int i = 0; i < 6; i++) { v[i] = xr[lane + 32 * i]; s += v[i]; s2 += v[i] * v[i]; }
#pragma unroll
    for (int o = 16; o; o >>= 1) {
        s  += __shfl_xor_sync(0xffffffffu, s, o);
        s2 += __shfl_xor_sync(0xffffffffu, s2, o);
    }
    float mu  = s * (1.f / CDIM);
    float var = s2 * (1.f / CDIM) - mu * mu;
    float rs = rsqrtf(var + 1e-3f);
    float* yr = y + warp * CDIM;
#pragma unroll
    for (int i = 0; i < 6; i++) {
        int c = lane + 32 * i;
        yr[c] = (v[i] - mu) * rs * g[c] + b[c];
    }
}

// ---------------- bf16 tensor-core GEMM: C = A(:,aoff:aoff+K) * B (+R) ----------------
// Block tile 128x64, BK=32, 256 threads = 8 warps (4 over M x 2 over N), warp tile 32x32.
// Double-buffered smem, ldmatrix fragments, mma.m16n8k16 bf16, fp32 accumulate.
#define LDAK 40     // bf16 pitch for As rows  (conflict-free ldmatrix: 80B -> 20-bank shift)
#define LDBN 72     // bf16 pitch for Bs rows  (144B -> 4-bank shift)
#define ASZ  (128 * LDAK)
#define BSZ  (32 * LDBN)
__global__ void __launch_bounds__(256) gemm_bf16(
    const float* __restrict__ A, int lda, int aoff,
    const float* __restrict__ B, int bstride,
    const float* __restrict__ R,
    float* __restrict__ C,
    int Nper, int Kpad, int Kreal, int M)
{
    __shared__ __nv_bfloat16 As[2 * ASZ];
    __shared__ __nv_bfloat16 Bs[2 * BSZ];

    int bz = blockIdx.z;
    A += (size_t)bz * Nper * lda;
    B += (size_t)bz * bstride;
    if (R) R += (size_t)bz * (size_t)Nper * M;
    C += (size_t)bz * (size_t)Nper * M;

    int tid = threadIdx.x;
    int row0 = blockIdx.y * 128;
    int col0 = blockIdx.x * 64;
    int warp = tid >> 5, lane = tid & 31;
    int wm = warp & 3, wn = warp >> 2;
    int g = lane >> 2, tig = lane & 3;
    bool mfull = (col0 + 64 <= M);

    unsigned as_base = (unsigned)__cvta_generic_to_shared(As);
    unsigned bs_base = (unsigned)__cvta_generic_to_shared(Bs);

    float4 fa[4];
    float4 fb[2];

    float acc[2][4][4];
#pragma unroll
    for (int mt = 0; mt < 2; mt++)
#pragma unroll
        for (int nt = 0; nt < 4; nt++)
#pragma unroll
            for (int i = 0; i < 4; i++) acc[mt][nt][i] = 0.f;

    // ---- loaders ----
    auto load_regs = [&](int k0) {
#pragma unroll
        for (int i = 0; i < 4; i++) {
            int id = tid + i * 256;
            int row = id >> 3;
            int kq = (id & 7) << 2;
            fa[i] = *reinterpret_cast<const float4*>(
                A + (size_t)(row0 + row) * lda + aoff + k0 + kq);
        }
#pragma unroll
        for (int i = 0; i < 2; i++) {
            int id = tid + i * 256;
            int kr = id >> 4;
            int nq = (id & 15) << 2;
            int kk = k0 + kr;
            if (mfull && kk < Kreal) {
                fb[i] = *reinterpret_cast<const float4*>(B + (size_t)kk * M + col0 + nq);
            } else {
                float4 v = make_float4(0.f, 0.f, 0.f, 0.f);
                if (kk < Kreal) {
                    const float* p = B + (size_t)kk * M;
                    if (col0 + nq + 0 < M) v.x = p[col0 + nq + 0];
                    if (col0 + nq + 1 < M) v.y = p[col0 + nq + 1];
                    if (col0 + nq + 2 < M) v.z = p[col0 + nq + 2];
                    if (col0 + nq + 3 < M) v.w = p[col0 + nq + 3];
                }
                fb[i] = v;
            }
        }
    };
    auto store_smem = [&](int buf) {
        __nv_bfloat16* as = As + buf * ASZ;
        __nv_bfloat16* bs = Bs + buf * BSZ;
#pragma unroll
        for (int i = 0; i < 4; i++) {
            int id = tid + i * 256;
            int row = id >> 3;
            int kq = (id & 7) << 2;
            __nv_bfloat162 p0 = __floats2bfloat162_rn(fa[i].x, fa[i].y);
            __nv_bfloat162 p1 = __floats2bfloat162_rn(fa[i].z, fa[i].w);
            *reinterpret_cast<__nv_bfloat162*>(as + row * LDAK + kq)     = p0;
            *reinterpret_cast<__nv_bfloat162*>(as + row * LDAK + kq + 2) = p1;
        }
#pragma unroll
        for (int i = 0; i < 2; i++) {
            int id = tid + i * 256;
            int kr = id >> 4;
            int nq = (id & 15) << 2;
            __nv_bfloat162 p0 = __floats2bfloat162_rn(fb[i].x, fb[i].y);
            __nv_bfloat162 p1 = __floats2bfloat162_rn(fb[i].z, fb[i].w);
            *reinterpret_cast<__nv_bfloat162*>(bs + kr * LDBN + nq)     = p0;
            *reinterpret_cast<__nv_bfloat162*>(bs + kr * LDBN + nq + 2) = p1;
        }
    };
    auto compute = [&](int buf) {
        unsigned abase = as_base + buf * (ASZ * 2);
        unsigned bbase = bs_base + buf * (BSZ * 2);
        int lrow = lane & 15, lhi = lane >> 4;
#pragma unroll
        for (int ks = 0; ks < 2; ks++) {
            unsigned afr[2][4];
#pragma unroll
            for (int mt = 0; mt < 2; mt++) {
                unsigned addr = abase +
                    ((wm * 32 + mt * 16 + lrow) * LDAK + ks * 16 + lhi * 8) * 2;
                ldsm4(afr[mt], addr);
            }
            unsigned bfr[2][4];
#pragma unroll
            for (int np = 0; np < 2; np++) {
                unsigned addr = bbase +
                    ((ks * 16 + lrow) * LDBN + wn * 32 + np * 16 + lhi * 8) * 2;
                ldsm4t(bfr[np], addr);
            }
#pragma unroll
            for (int mt = 0; mt < 2; mt++)
#pragma unroll
                for (int np = 0; np < 2; np++) {
                    mma_bf16(acc[mt][np * 2 + 0], afr[mt], bfr[np][0], bfr[np][1]);
                    mma_bf16(acc[mt][np * 2 + 1], afr[mt], bfr[np][2], bfr[np][3]);
                }
        }
    };

    // ---- pipelined mainloop ----
    load_regs(0);
    store_smem(0);
    __syncthreads();
    int buf = 0;
    for (int k0 = 0; k0 < Kpad; k0 += 32) {
        bool has_next = (k0 + 32 < Kpad);
        if (has_next) load_regs(k0 + 32);
        compute(buf);
        if (has_next) {
            store_smem(buf ^ 1);
            __syncthreads();
            buf ^= 1;
        }
    }

    // ---- epilogue ----
#pragma unroll
    for (int mt = 0; mt < 2; mt++) {
        size_t r = (size_t)row0 + wm * 32 + mt * 16 + g;
#pragma unroll
        for (int nt = 0; nt < 4; nt++) {
            int col = col0 + wn * 32 + nt * 8 + tig * 2;
            float* p0 = C + r * M + col;
            float* p1 = C + (r + 8) * M + col;
            if (mfull) {
                float2 o0 = make_float2(acc[mt][nt][0], acc[mt][nt][1]);
                float2 o1 = make_float2(acc[mt][nt][2], acc[mt][nt][3]);
                if (R) {
                    float2 r0 = *reinterpret_cast<const float2*>(R + r * M + col);
                    float2 r1 = *reinterpret_cast<const float2*>(R + (r + 8) * M + col);
                    o0.x += r0.x; o0.y += r0.y; o1.x += r1.x; o1.y += r1.y;
                }
                *reinterpret_cast<float2*>(p0) = o0;
                *reinterpret_cast<float2*>(p1) = o1;
            } else if (col < M) {  // M even; col even => col+1 < M too
                float o0 = acc[mt][nt][0], o1 = acc[mt][nt][1];
                float o2 = acc[mt][nt][2], o3 = acc[mt][nt][3];
                if (R) {
                    o0 += R[r * M + col]; o1 += R[r * M + col + 1];
                    o2 += R[(r + 8) * M + col]; o3 += R[(r + 8) * M + col + 1];
                }
                p0[0] = o0; p0[1] = o1; p1[0] = o2; p1[1] = o3;
            }
        }
    }
}

// ---------------- depthwise 3x3 SAME conv, NHWC, one block per pixel ----------------
__global__ void dwconv_kernel(const float* __restrict__ in, const float* __restrict__ w,
                              float* __restrict__ out, int C) {
    int p = blockIdx.x;
    int c = threadIdx.x;
    int b = p >> 14, hw = p & 16383, yy = hw >> 7, xx = hw & 127;
    float acc = 0.f;
#pragma unroll
    for (int ky = -1; ky <= 1; ky++) {
        int yn = yy + ky;
        if ((unsigned)yn >= HH) continue;
#pragma unroll
        for (int kx = -1; kx <= 1; kx++) {
            int xn = xx + kx;
            if ((unsigned)xn >= WW) continue;
            size_t idx = ((size_t)(b << 14) + (yn << 7) + xn) * C + c;
            acc += in[idx] * w[((ky + 1) * 3 + (kx + 1)) * C + c];
        }
    }
    out[(size_t)p * C + c] = acc;
}

// ---------------- FFN depthwise 3x3 + exact-GELU gating fused ----------------
__global__ void dwconv_ffn_gate(const float* __restrict__ in, const float* __restrict__ w,
                                float* __restrict__ out) {
    int p = blockIdx.x;
    int c = threadIdx.x;          // blockDim = 512
    if (c >= HID) {               // zero-pad cols 510,511 so Kpad=512 GEMM reads zeros
        out[(size_t)p * UGLD + c] = 0.f;
        return;
    }
    int b = p >> 14, hw = p & 16383, yy = hw >> 7, xx = hw & 127;
    float a1 = 0.f, a2 = 0.f;
#pragma unroll
    for (int ky = -1; ky <= 1; ky++) {
        int yn = yy + ky;
        if ((unsigned)yn >= HH) continue;
#pragma unroll
        for (int kx = -1; kx <= 1; kx++) {
            int xn = xx + kx;
            if ((unsigned)xn >= WW) continue;
            size_t idx = ((size_t)(b << 14) + (yn << 7) + xn) * HID2;
            int wi = ((ky + 1) * 3 + (kx + 1)) * HID2;
            a1 += in[idx + c]        * w[wi + c];
            a2 += in[idx + HID + c]  * w[wi + HID + c];
        }
    }
    float gl = 0.5f * a1 * (1.f + erff(a1 * 0.70710678118654752f));
    out[(size_t)p * UGLD + c] = gl * a2;
}

// ---------------- attention: partial K^T Q (deterministic two-stage) ----------------
// v2: per-pixel scale hoist (rsqrtf once per pixel), float4 staging, 16 rows/stage.
__global__ void __launch_bounds__(256) attn_partial(
        const float* __restrict__ qkv,
        const float* __restrict__ mq, const float* __restrict__ vq,
        const float* __restrict__ mk, const float* __restrict__ vk,
        float* __restrict__ part) {
    int chunk = blockIdx.x, h = blockIdx.y, b = blockIdx.z;
    __shared__ __align__(16) float sq[16][32];
    __shared__ float sk[16][32];
    __shared__ float sm[2][16];   // mq, mk
    __shared__ float sr[2][16];   // rsqrt(vq), rsqrt(vk)
    int tid = threadIdx.x;
    int c  = tid >> 3;
    int d0 = (tid & 7) << 2;
    size_t rowbase = ((size_t)b * NPB + chunk * 1024) * C3;
    int hwbase = chunk * 1024;
    int nn_l = tid >> 4;          // 0..15 (staging row)
    int prt  = tid & 15;          // 0..15 (staging slot)
    float acc0 = 0.f, acc1 = 0.f, acc2 = 0.f, acc3 = 0.f;

    for (int n0 = 0; n0 < 1024; n0 += 16) {
        // phase A: per-pixel scales (32 threads)
        if (tid < 32) {
            int qk = tid >> 4;          // 0=q, 1=k
            int nn = tid & 15;
            int hw = hwbase + n0 + nn;
            if (qk == 0) { sm[0][nn] = mq[hw]; sr[0][nn] = rsqrtf(vq[hw]); }
            else         { sm[1][nn] = mk[hw]; sr[1][nn] = rsqrtf(vk[hw]); }
        }
        __syncthreads();
        // phase B: stage 16 rows of q,k (float4 per thread)
        {
            size_t row = rowbase + (size_t)(n0 + nn_l) * C3;
            if (prt < 8) {
                float4 v = *reinterpret_cast<const float4*>(&qkv[row + h * HD + prt * 4]);
                float m = sm[0][nn_l], rs = sr[0][nn_l];
                float* d = &sq[nn_l][prt * 4];
                d[0] = (v.x - m) * rs; d[1] = (v.y - m) * rs;
                d[2] = (v.z - m) * rs; d[3] = (v.w - m) * rs;
            } else {
                float4 v = *reinterpret_cast<const float4*>(
                    &qkv[row + CDIM + h * HD + (prt - 8) * 4]);
                float m = sm[1][nn_l], rs = sr[1][nn_l];
                float* d = &sk[nn_l][(prt - 8) * 4];
                d[0] = (v.x - m) * rs; d[1] = (v.y - m) * rs;
                d[2] = (v.z - m) * rs; d[3] = (v.w - m) * rs;
            }
        }
        __syncthreads();
        // phase C: accumulate outer products
#pragma unroll
        for (int nn = 0; nn < 16; nn++) {
            float kv = sk[nn][c];
            float4 qv = *reinterpret_cast<const float4*>(&sq[nn][d0]);
            acc0 += kv * qv.x; acc1 += kv * qv.y; acc2 += kv * qv.z; acc3 += kv * qv.w;
        }
        __syncthreads();
    }
    float* o = part + (((size_t)(b * HEADS + h) * 16 + chunk) * 1024) + tid * 4;
    o[0] = acc0; o[1] = acc1; o[2] = acc2; o[3] = acc3;
}

// ---------------- reduce partials + temp + softmax over axis c ----------------
__global__ void softmax_kernel(const float* __restrict__ part, const float* __restrict__ temp,
                               float* __restrict__ attn) {
    int bh = blockIdx.x;            // 48
    int h = bh % HEADS;
    int d = threadIdx.x;            // 32
    float t = temp[h];
    float v[32];
#pragma unroll
    for (int c = 0; c < 32; c++) {
        float s = 0.f;
        for (int ch = 0; ch < 16; ch++)
            s += part[((size_t)bh * 16 + ch) * 1024 + c * 32 + d];
        v[c] = s * t;
    }
    float m = -1e30f;
#pragma unroll
    for (int c = 0; c < 32; c++) m = fmaxf(m, v[c]);
    float sum = 0.f;
#pragma unroll
    for (int c = 0; c < 32; c++) { v[c] = expf(v[c] - m); sum += v[c]; }
    float inv = 1.f / sum;
#pragma unroll
    for (int c = 0; c < 32; c++)
        attn[(size_t)bh * 1024 + c * 32 + d] = v[c] * inv;
}

// ---------------- fold attn into w_proj ----------------
__global__ void w2_kernel(const float* __restrict__ attn, const float* __restrict__ wproj,
                          float* __restrict__ W2) {
    int bh = blockIdx.x;            // 48
    int b = bh / HEADS, h = bh % HEADS;
    __shared__ float sA[32][32];
    __shared__ float sW[32][192];
    int tid = threadIdx.x;          // 192
    for (int t = tid; t < 1024; t += 192)
        sA[t >> 5][t & 31] = attn[(size_t)bh * 1024 + t];
    for (int dd = 0; dd < 32; dd++)
        sW[dd][tid] = wproj[(h * HD + dd) * CDIM + tid];
    __syncthreads();
    int o = tid;
    for (int c = 0; c < 32; c++) {
        float acc = 0.f;
#pragma unroll
        for (int dd = 0; dd < 32; dd++) acc += sA[c][dd] * sW[dd][o];
        W2[((size_t)b * CDIM + h * HD + c) * CDIM + o] = acc;
    }
}

// ---------------- launch ----------------
extern "C" void kernel_launch(void* const* d_in, const int* in_sizes, int n_in,
                              void* d_out, int out_size) {
    const float* x       = (const float*)d_in[0];
    const float* g1      = (const float*)d_in[1];
    const float* b1      = (const float*)d_in[2];
    const float* w_qkv   = (const float*)d_in[3];
    const float* w_qkv_dw= (const float*)d_in[4];
    const float* temp    = (const float*)d_in[5];
    const float* mean_q  = (const float*)d_in[6];
    const float* var_q   = (const float*)d_in[7];
    const float* mean_k  = (const float*)d_in[8];
    const float* var_k   = (const float*)d_in[9];
    const float* w_proj  = (const float*)d_in[10];
    const float* g2      = (const float*)d_in[11];
    const float* b2      = (const float*)d_in[12];
    const float* w_in    = (const float*)d_in[13];
    const float* w_ffn_dw= (const float*)d_in[14];
    const float* w_out   = (const float*)d_in[15];
    float* out = (float*)d_out;

    float *p_y, *p_qkvp, *p_qkv, *p_part, *p_attn, *p_W2, *p_x1, *p_upre, *p_ug;
    cudaGetSymbolAddress((void**)&p_y,    g_y);
    cudaGetSymbolAddress((void**)&p_qkvp, g_qkv_pre);
    cudaGetSymbolAddress((void**)&p_qkv,  g_qkv);
    cudaGetSymbolAddress((void**)&p_part, g_part);
    cudaGetSymbolAddress((void**)&p_attn, g_attn);
    cudaGetSymbolAddress((void**)&p_W2,   g_W2);
    cudaGetSymbolAddress((void**)&p_x1,   g_x1);
    cudaGetSymbolAddress((void**)&p_upre, g_upre);
    cudaGetSymbolAddress((void**)&p_ug,   g_ug);

    // 1. LN1
    ln_kernel<<<NPIX / 8, 256>>>(x, g1, b1, p_y);
    // 2. qkv = y @ w_qkv   [131072,192]x[192,576]
    gemm_bf16<<<dim3(C3 / 64, NPIX / 128, 1), 256>>>(p_y, CDIM, 0, w_qkv, 0, nullptr,
                                                     p_qkvp, NPIX, CDIM, CDIM, C3);
    // 3. depthwise 3x3 on qkv
    dwconv_kernel<<<NPIX, C3>>>(p_qkvp, w_qkv_dw, p_qkv, C3);
    // 4. K^T Q partials
    attn_partial<<<dim3(16, HEADS, BATCH), 256>>>(p_qkv, mean_q, var_q, mean_k, var_k, p_part);
    // 5. reduce + temp + softmax(axis=-2)
    softmax_kernel<<<48, 32>>>(p_part, temp, p_attn);
    // 6. fold attn into w_proj
    w2_kernel<<<48, 192>>>(p_attn, w_proj, p_W2);
    // 7. x1 = x + V @ W2[b]   (batched, A = qkv cols 384..575)
    gemm_bf16<<<dim3(CDIM / 64, NPB / 128, BATCH), 256>>>(p_qkv, C3, 384, p_W2, CDIM * CDIM,
                                                          x, p_x1, NPB, CDIM, CDIM, CDIM);
    // 8. LN2
    ln_kernel<<<NPIX / 8, 256>>>(p_x1, g2, b2, p_y);
    // 9. u_pre = y @ w_in   [131072,192]x[192,1020]
    gemm_bf16<<<dim3((HID2 + 63) / 64, NPIX / 128, 1), 256>>>(p_y, CDIM, 0, w_in, 0, nullptr,
                                                              p_upre, NPIX, CDIM, CDIM, HID2);
    // 10. depthwise 3x3 + GELU gate fused -> ug [131072,510] (lda 512, zero-padded)
    dwconv_ffn_gate<<<NPIX, 512>>>(p_upre, w_ffn_dw, p_ug);
    // 11. out = x1 + ug @ w_out   [131072,510(pad512)]x[510,192]
    gemm_bf16<<<dim3(CDIM / 64, NPIX / 128, 1), 256>>>(p_ug, UGLD, 0, w_out, 0, p_x1,
                                                       out, NPIX, UGLD, HID, CDIM);
    (void)in_sizes; (void)n_in; (void)out_size;
}

// round 7
// speedup vs baseline: 1.2031x; 1.2031x over previous
#include <cuda_runtime.h>
#include <cuda_bf16.h>
#include <math.h>

#define NPIX   131072
#define BATCH  8
#define HH     128
#define WW     128
#define CDIM   192
#define C3     576
#define HEADS  6
#define HD     32
#define HID    510
#define HID2   1020
#define UPLD   1024       // padded M for FFN-in GEMM output
#define UGLD   512        // padded lda for gated ffn activation
#define NPB    16384

// ---------------- scratch (device globals) ----------------
__device__ __align__(128) __nv_bfloat16 g_y[(size_t)NPIX * CDIM];
__device__ __align__(128) float g_qkv_pre[(size_t)NPIX * C3];
__device__ __align__(128) float g_qkn[(size_t)NPIX * 384];      // normalized q,k
__device__ __align__(128) __nv_bfloat16 g_v[(size_t)NPIX * CDIM];
__device__ __align__(128) float g_part[48 * 64 * 1024];
__device__ __align__(128) float g_attn[48 * 1024];
__device__ __align__(128) __nv_bfloat16 g_W2[BATCH * CDIM * CDIM];
__device__ __align__(128) float g_x1[(size_t)NPIX * CDIM];
__device__ __align__(128) __nv_bfloat16 g_upre[(size_t)NPIX * UPLD];
__device__ __align__(128) __nv_bfloat16 g_ug[(size_t)NPIX * UGLD];
// bf16 weights (padded)
__device__ __align__(128) __nv_bfloat16 g_wqkv[CDIM * C3];
__device__ __align__(128) __nv_bfloat16 g_win[CDIM * UPLD];     // cols 1020..1023 zero
__device__ __align__(128) __nv_bfloat16 g_wout[UGLD * CDIM];    // rows 510,511 zero

// ---------------- asm helpers ----------------
__device__ __forceinline__ void ldsm4(unsigned* r, unsigned addr) {
    asm volatile("ldmatrix.sync.aligned.m8n8.x4.shared.b16 {%0,%1,%2,%3}, [%4];"
                 : "=r"(r[0]), "=r"(r[1]), "=r"(r[2]), "=r"(r[3]) : "r"(addr));
}
__device__ __forceinline__ void ldsm4t(unsigned* r, unsigned addr) {
    asm volatile("ldmatrix.sync.aligned.m8n8.x4.trans.shared.b16 {%0,%1,%2,%3}, [%4];"
                 : "=r"(r[0]), "=r"(r[1]), "=r"(r[2]), "=r"(r[3]) : "r"(addr));
}
__device__ __forceinline__ void mma_bf16(float* d, const unsigned* a, unsigned b0, unsigned b1) {
    asm volatile(
        "mma.sync.aligned.m16n8k16.row.col.f32.bf16.bf16.f32 "
        "{%0,%1,%2,%3},{%4,%5,%6,%7},{%8,%9},{%0,%1,%2,%3};"
        : "+f"(d[0]), "+f"(d[1]), "+f"(d[2]), "+f"(d[3])
        : "r"(a[0]), "r"(a[1]), "r"(a[2]), "r"(a[3]), "r"(b0), "r"(b1));
}
__device__ __forceinline__ void cp16(unsigned dst, const void* src) {
    asm volatile("cp.async.cg.shared.global [%0], [%1], 16;" :: "r"(dst), "l"(src));
}
__device__ __forceinline__ void cp_commit() { asm volatile("cp.async.commit_group;"); }
__device__ __forceinline__ void cp_wait1() { asm volatile("cp.async.wait_group 1;"); }
__device__ __forceinline__ void cp_wait0() { asm volatile("cp.async.wait_group 0;"); }

// ---------------- weight convert + pad: dst[drows,dcols] = bf16(src[srows,scols]), else 0
__global__ void cvt_pad(const float* __restrict__ src, int srows, int scols,
                        __nv_bfloat16* __restrict__ dst, int dcols) {
    size_t i = (size_t)blockIdx.x * 256 + threadIdx.x;
    int r = (int)(i / dcols), cc = (int)(i % dcols);
    float v = (cc < scols && r * scols + cc >= 0) ? 0.f : 0.f;
    v = (cc < scols) ? src[(size_t)r * scols + cc] : 0.f;
    dst[i] = __float2bfloat16(v);
}
// row-padded variant (rows >= srows -> 0)
__global__ void cvt_pad_rows(const float* __restrict__ src, int srows, int cols,
                             __nv_bfloat16* __restrict__ dst) {
    size_t i = (size_t)blockIdx.x * 256 + threadIdx.x;
    int r = (int)(i / cols), cc = (int)(i % cols);
    float v = (r < srows) ? src[(size_t)r * cols + cc] : 0.f;
    dst[i] = __float2bfloat16(v);
}

// ---------------- LayerNorm -> bf16 output ----------------
__global__ void ln_kernel(const float* __restrict__ x, const float* __restrict__ g,
                          const float* __restrict__ b, __nv_bfloat16* __restrict__ y) {
    size_t warp = ((size_t)blockIdx.x * blockDim.x + threadIdx.x) >> 5;
    int lane = threadIdx.x & 31;
    const float* xr = x + warp * CDIM;
    float v[6]; float s = 0.f, s2 = 0.f;
#pragma unroll
    for (int i = 0; i < 6; i++) { v[i] = xr[lane + 32 * i]; s += v[i]; s2 += v[i] * v[i]; }
#pragma unroll
    for (int o = 16; o; o >>= 1) {
        s  += __shfl_xor_sync(0xffffffffu, s, o);
        s2 += __shfl_xor_sync(0xffffffffu, s2, o);
    }
    float mu  = s * (1.f / CDIM);
    float var = s2 * (1.f / CDIM) - mu * mu;
    float rs = rsqrtf(var + 1e-3f);
    __nv_bfloat16* yr = y + warp * CDIM;
#pragma unroll
    for (int i = 0; i < 6; i++) {
        int c = lane + 32 * i;
        yr[c] = __float2bfloat16((v[i] - mu) * rs * g[c] + b[c]);
    }
}

// ---------------- bf16 GEMM, cp.async 3-stage: C = A*B (+R) ----------------
// A [Nper,lda] bf16, B [K,ldb] bf16 (bstride per z), out fp32 (+R) or bf16.
// All dims padded: M%64==0, K%32==0, rows%128==0. Tile 128x64, 256 threads.
#define LDAK 40
#define LDBN 72
#define ASZE (128 * LDAK)
#define BSZE (32 * LDBN)
__global__ void __launch_bounds__(256) gemm_bf16(
    const __nv_bfloat16* __restrict__ A, int lda,
    const __nv_bfloat16* __restrict__ B, int ldb, long long bstride,
    const float* __restrict__ R,
    void* __restrict__ Cout, int obf16,
    int Nper, int K, int M)
{
    __shared__ __nv_bfloat16 As[3 * ASZE];
    __shared__ __nv_bfloat16 Bs[3 * BSZE];

    int bz = blockIdx.z;
    A += (size_t)bz * Nper * lda;
    B += (size_t)bz * bstride;
    size_t cbase = (size_t)bz * Nper * M;
    if (R) R += cbase;

    int tid = threadIdx.x;
    int row0 = blockIdx.y * 128;
    int col0 = blockIdx.x * 64;
    int warp = tid >> 5, lane = tid & 31;
    int wm = warp & 3, wn = warp >> 2;
    int g = lane >> 2, tig = lane & 3;
    int lrow = lane & 15, lhi = lane >> 4;

    unsigned as_u = (unsigned)__cvta_generic_to_shared(As);
    unsigned bs_u = (unsigned)__cvta_generic_to_shared(Bs);

    // load mappings
    int ar0 = tid >> 2, ak0 = (tid & 3) << 3;       // + second chunk at tid+256
    int ar1 = (tid + 256) >> 2, ak1 = ((tid + 256) & 3) << 3;
    int bkr = tid >> 3, bnc = (tid & 7) << 3;

    float acc[2][4][4];
#pragma unroll
    for (int mt = 0; mt < 2; mt++)
#pragma unroll
        for (int nt = 0; nt < 4; nt++)
#pragma unroll
            for (int i = 0; i < 4; i++) acc[mt][nt][i] = 0.f;

    auto issue = [&](int s, int k0) {
        unsigned ab = as_u + s * (ASZE * 2);
        unsigned bb = bs_u + s * (BSZE * 2);
        cp16(ab + (ar0 * LDAK + ak0) * 2, A + (size_t)(row0 + ar0) * lda + k0 + ak0);
        cp16(ab + (ar1 * LDAK + ak1) * 2, A + (size_t)(row0 + ar1) * lda + k0 + ak1);
        cp16(bb + (bkr * LDBN + bnc) * 2, B + (size_t)(k0 + bkr) * ldb + col0 + bnc);
        cp_commit();
    };
    auto compute = [&](int s) {
        unsigned ab = as_u + s * (ASZE * 2);
        unsigned bb = bs_u + s * (BSZE * 2);
#pragma unroll
        for (int ks = 0; ks < 2; ks++) {
            unsigned afr[2][4];
#pragma unroll
            for (int mt = 0; mt < 2; mt++)
                ldsm4(afr[mt], ab + ((wm * 32 + mt * 16 + lrow) * LDAK + ks * 16 + lhi * 8) * 2);
            unsigned bfr[2][4];
#pragma unroll
            for (int np = 0; np < 2; np++)
                ldsm4t(bfr[np], bb + ((ks * 16 + lrow) * LDBN + wn * 32 + np * 16 + lhi * 8) * 2);
#pragma unroll
            for (int mt = 0; mt < 2; mt++)
#pragma unroll
                for (int np = 0; np < 2; np++) {
                    mma_bf16(acc[mt][np * 2 + 0], afr[mt], bfr[np][0], bfr[np][1]);
                    mma_bf16(acc[mt][np * 2 + 1], afr[mt], bfr[np][2], bfr[np][3]);
                }
        }
    };

    int kt = K >> 5;
    issue(0, 0);
    issue(1, 32);
    for (int it = 0; it < kt; it++) {
        if (it + 2 < kt) cp_wait1(); else cp_wait0();
        __syncthreads();
        if (it + 2 < kt) issue((it + 2) % 3, (it + 2) * 32);
        compute(it % 3);
    }

    // epilogue (no tails: M%64==0)
#pragma unroll
    for (int mt = 0; mt < 2; mt++) {
        size_t r = (size_t)row0 + wm * 32 + mt * 16 + g;
#pragma unroll
        for (int nt = 0; nt < 4; nt++) {
            int col = col0 + wn * 32 + nt * 8 + tig * 2;
            if (obf16) {
                __nv_bfloat16* C = (__nv_bfloat16*)Cout + cbase;
                *reinterpret_cast<__nv_bfloat162*>(C + r * M + col) =
                    __floats2bfloat162_rn(acc[mt][nt][0], acc[mt][nt][1]);
                *reinterpret_cast<__nv_bfloat162*>(C + (r + 8) * M + col) =
                    __floats2bfloat162_rn(acc[mt][nt][2], acc[mt][nt][3]);
            } else {
                float* C = (float*)Cout + cbase;
                float2 o0 = make_float2(acc[mt][nt][0], acc[mt][nt][1]);
                float2 o1 = make_float2(acc[mt][nt][2], acc[mt][nt][3]);
                if (R) {
                    float2 r0 = *reinterpret_cast<const float2*>(R + r * M + col);
                    float2 r1 = *reinterpret_cast<const float2*>(R + (r + 8) * M + col);
                    o0.x += r0.x; o0.y += r0.y; o1.x += r1.x; o1.y += r1.y;
                }
                *reinterpret_cast<float2*>(C + r * M + col) = o0;
                *reinterpret_cast<float2*>(C + (r + 8) * M + col) = o1;
            }
        }
    }
}

// ---------------- qkv dwconv + q/k normalization + v->bf16 ----------------
__global__ void dwconv_qkv(const float* __restrict__ in, const float* __restrict__ w,
                           const float* __restrict__ mq, const float* __restrict__ vq,
                           const float* __restrict__ mk, const float* __restrict__ vk,
                           float* __restrict__ qkn, __nv_bfloat16* __restrict__ v) {
    int p = blockIdx.x;
    int c = threadIdx.x;    // 576
    int b = p >> 14, hw = p & 16383, yy = hw >> 7, xx = hw & 127;
    float acc = 0.f;
#pragma unroll
    for (int ky = -1; ky <= 1; ky++) {
        int yn = yy + ky;
        if ((unsigned)yn >= HH) continue;
#pragma unroll
        for (int kx = -1; kx <= 1; kx++) {
            int xn = xx + kx;
            if ((unsigned)xn >= WW) continue;
            size_t idx = ((size_t)(b << 14) + (yn << 7) + xn) * C3 + c;
            acc += in[idx] * w[((ky + 1) * 3 + (kx + 1)) * C3 + c];
        }
    }
    if (c < 192) {
        qkn[(size_t)p * 384 + c] = (acc - mq[hw]) * rsqrtf(vq[hw]);
    } else if (c < 384) {
        qkn[(size_t)p * 384 + c] = (acc - mk[hw]) * rsqrtf(vk[hw]);
    } else {
        v[(size_t)p * CDIM + (c - 384)] = __float2bfloat16(acc);
    }
}

// ---------------- FFN dwconv + GELU gate: bf16 in [NPIX,1024], bf16 out [NPIX,512] ----
__global__ void dwconv_ffn_gate(const __nv_bfloat16* __restrict__ in,
                                const float* __restrict__ w,
                                __nv_bfloat16* __restrict__ out) {
    int p = blockIdx.x;
    int c = threadIdx.x;          // 512
    if (c >= HID) { out[(size_t)p * UGLD + c] = __float2bfloat16(0.f); return; }
    int b = p >> 14, hw = p & 16383, yy = hw >> 7, xx = hw & 127;
    float a1 = 0.f, a2 = 0.f;
#pragma unroll
    for (int ky = -1; ky <= 1; ky++) {
        int yn = yy + ky;
        if ((unsigned)yn >= HH) continue;
#pragma unroll
        for (int kx = -1; kx <= 1; kx++) {
            int xn = xx + kx;
            if ((unsigned)xn >= WW) continue;
            size_t idx = ((size_t)(b << 14) + (yn << 7) + xn) * UPLD;
            int wi = ((ky + 1) * 3 + (kx + 1)) * HID2;
            a1 += __bfloat162float(in[idx + c])       * w[wi + c];
            a2 += __bfloat162float(in[idx + HID + c]) * w[wi + HID + c];
        }
    }
    float gl = 0.5f * a1 * (1.f + erff(a1 * 0.70710678118654752f));
    out[(size_t)p * UGLD + c] = __float2bfloat16(gl * a2);
}

// ---------------- attention K^T Q partials: 2x4 register tile, pre-normalized input ----
// grid (32 chunks, 6 heads, 8 batch) block 256 (2 sub-tiles of 128 threads x 256 rows)
__global__ void __launch_bounds__(256) attn_partial(
        const float* __restrict__ qkn, float* __restrict__ part) {
    int chunk = blockIdx.x, h = blockIdx.y, b = blockIdx.z;
    __shared__ __align__(16) float sq[2][16][32];
    __shared__ __align__(16) float sk[2][16][32];
    int tid = threadIdx.x;
    int sub = tid >> 7;
    int slot = tid & 127;
    int c0 = (slot >> 3) << 1;    // 0,2,..,30
    int d0 = (slot & 7) << 2;     // 0,4,..,28
    size_t rowbase = ((size_t)b * NPB + chunk * 512 + sub * 256) * 384;
    float a0[4] = {}, a1[4] = {};

    for (int n0 = 0; n0 < 256; n0 += 16) {
#pragma unroll
        for (int j = 0; j < 2; j++) {
            int sid = slot + j * 128;
            int nn = sid >> 4;
            int prt = sid & 15;
            const float* src = qkn + rowbase + (size_t)(n0 + nn) * 384 +
                               ((prt & 8) ? 192 : 0) + h * HD + (prt & 7) * 4;
            float4 val = *reinterpret_cast<const float4*>(src);
            float* dst = (prt & 8) ? &sk[sub][nn][(prt & 7) * 4]
                                   : &sq[sub][nn][(prt & 7) * 4];
            *reinterpret_cast<float4*>(dst) = val;
        }
        __syncthreads();
#pragma unroll
        for (int nn = 0; nn < 16; nn++) {
            float kv0 = sk[sub][nn][c0];
            float kv1 = sk[sub][nn][c0 + 1];
            float4 qv = *reinterpret_cast<const float4*>(&sq[sub][nn][d0]);
            a0[0] += kv0 * qv.x; a0[1] += kv0 * qv.y; a0[2] += kv0 * qv.z; a0[3] += kv0 * qv.w;
            a1[0] += kv1 * qv.x; a1[1] += kv1 * qv.y; a1[2] += kv1 * qv.z; a1[3] += kv1 * qv.w;
        }
        __syncthreads();
    }
    float* o = part + ((size_t)(b * HEADS + h) * 64 + chunk * 2 + sub) * 1024;
    *reinterpret_cast<float4*>(&o[c0 * 32 + d0])       = make_float4(a0[0], a0[1], a0[2], a0[3]);
    *reinterpret_cast<float4*>(&o[(c0 + 1) * 32 + d0]) = make_float4(a1[0], a1[1], a1[2], a1[3]);
}

// ---------------- reduce partials + temp + softmax over axis c ----------------
__global__ void softmax_kernel(const float* __restrict__ part, const float* __restrict__ temp,
                               float* __restrict__ attn) {
    int bh = blockIdx.x;            // 48
    int h = bh % HEADS;
    int d = threadIdx.x;            // 32
    float t = temp[h];
    float v[32];
#pragma unroll
    for (int c = 0; c < 32; c++) {
        float s = 0.f;
        for (int ch = 0; ch < 64; ch++)
            s += part[((size_t)bh * 64 + ch) * 1024 + c * 32 + d];
        v[c] = s * t;
    }
    float m = -1e30f;
#pragma unroll
    for (int c = 0; c < 32; c++) m = fmaxf(m, v[c]);
    float sum = 0.f;
#pragma unroll
    for (int c = 0; c < 32; c++) { v[c] = expf(v[c] - m); sum += v[c]; }
    float inv = 1.f / sum;
#pragma unroll
    for (int c = 0; c < 32; c++)
        attn[(size_t)bh * 1024 + c * 32 + d] = v[c] * inv;
}

// ---------------- fold attn into w_proj -> bf16 W2 ----------------
__global__ void w2_kernel(const float* __restrict__ attn, const float* __restrict__ wproj,
                          __nv_bfloat16* __restrict__ W2) {
    int bh = blockIdx.x;            // 48
    int b = bh / HEADS, h = bh % HEADS;
    __shared__ float sA[32][32];
    __shared__ float sW[32][192];
    int tid = threadIdx.x;          // 192
    for (int t = tid; t < 1024; t += 192)
        sA[t >> 5][t & 31] = attn[(size_t)bh * 1024 + t];
    for (int dd = 0; dd < 32; dd++)
        sW[dd][tid] = wproj[(h * HD + dd) * CDIM + tid];
    __syncthreads();
    int o = tid;
    for (int c = 0; c < 32; c++) {
        float acc = 0.f;
#pragma unroll
        for (int dd = 0; dd < 32; dd++) acc += sA[c][dd] * sW[dd][o];
        W2[((size_t)b * CDIM + h * HD + c) * CDIM + o] = __float2bfloat16(acc);
    }
}

// ---------------- launch ----------------
extern "C" void kernel_launch(void* const* d_in, const int* in_sizes, int n_in,
                              void* d_out, int out_size) {
    const float* x       = (const float*)d_in[0];
    const float* g1      = (const float*)d_in[1];
    const float* b1      = (const float*)d_in[2];
    const float* w_qkv   = (const float*)d_in[3];
    const float* w_qkv_dw= (const float*)d_in[4];
    const float* temp    = (const float*)d_in[5];
    const float* mean_q  = (const float*)d_in[6];
    const float* var_q   = (const float*)d_in[7];
    const float* mean_k  = (const float*)d_in[8];
    const float* var_k   = (const float*)d_in[9];
    const float* w_proj  = (const float*)d_in[10];
    const float* g2      = (const float*)d_in[11];
    const float* b2      = (const float*)d_in[12];
    const float* w_in    = (const float*)d_in[13];
    const float* w_ffn_dw= (const float*)d_in[14];
    const float* w_out   = (const float*)d_in[15];
    float* out = (float*)d_out;

    __nv_bfloat16 *p_y, *p_v, *p_W2, *p_upre, *p_ug, *p_wqkv, *p_win, *p_wout;
    float *p_qkvp, *p_qkn, *p_part, *p_attn, *p_x1;
    cudaGetSymbolAddress((void**)&p_y,    g_y);
    cudaGetSymbolAddress((void**)&p_qkvp, g_qkv_pre);
    cudaGetSymbolAddress((void**)&p_qkn,  g_qkn);
    cudaGetSymbolAddress((void**)&p_v,    g_v);
    cudaGetSymbolAddress((void**)&p_part, g_part);
    cudaGetSymbolAddress((void**)&p_attn, g_attn);
    cudaGetSymbolAddress((void**)&p_W2,   g_W2);
    cudaGetSymbolAddress((void**)&p_x1,   g_x1);
    cudaGetSymbolAddress((void**)&p_upre, g_upre);
    cudaGetSymbolAddress((void**)&p_ug,   g_ug);
    cudaGetSymbolAddress((void**)&p_wqkv, g_wqkv);
    cudaGetSymbolAddress((void**)&p_win,  g_win);
    cudaGetSymbolAddress((void**)&p_wout, g_wout);

    // 0. weight conversion (bf16, padded)
    cvt_pad<<<(CDIM * C3) / 256, 256>>>(w_qkv, CDIM, C3, p_wqkv, C3);
    cvt_pad<<<(CDIM * UPLD) / 256, 256>>>(w_in, CDIM, HID2, p_win, UPLD);
    cvt_pad_rows<<<(UGLD * CDIM) / 256, 256>>>(w_out, HID, CDIM, p_wout);

    // 1. LN1 -> bf16
    ln_kernel<<<NPIX / 8, 256>>>(x, g1, b1, p_y);
    // 2. qkv = y @ w_qkv  (bf16 x bf16 -> fp32)
    gemm_bf16<<<dim3(C3 / 64, NPIX / 128, 1), 256>>>(p_y, CDIM, p_wqkv, C3, 0, nullptr,
                                                     p_qkvp, 0, NPIX, CDIM, C3);
    // 3. dwconv 3x3 + q/k normalization + v bf16
    dwconv_qkv<<<NPIX, C3>>>(p_qkvp, w_qkv_dw, mean_q, var_q, mean_k, var_k, p_qkn, p_v);
    // 4. K^T Q partials
    attn_partial<<<dim3(32, HEADS, BATCH), 256>>>(p_qkn, p_part);
    // 5. softmax(axis=-2)
    softmax_kernel<<<48, 32>>>(p_part, temp, p_attn);
    // 6. fold attn into w_proj -> bf16 W2
    w2_kernel<<<48, 192>>>(p_attn, w_proj, p_W2);
    // 7. x1 = x + V @ W2[b]
    gemm_bf16<<<dim3(CDIM / 64, NPB / 128, BATCH), 256>>>(p_v, CDIM, p_W2, CDIM,
                                                          (long long)CDIM * CDIM, x,
                                                          p_x1, 0, NPB, CDIM, CDIM);
    // 8. LN2 -> bf16
    ln_kernel<<<NPIX / 8, 256>>>(p_x1, g2, b2, p_y);
    // 9. u_pre = y @ w_in (bf16 out, padded M=1024)
    gemm_bf16<<<dim3(UPLD / 64, NPIX / 128, 1), 256>>>(p_y, CDIM, p_win, UPLD, 0, nullptr,
                                                       p_upre, 1, NPIX, CDIM, UPLD);
    // 10. dwconv + GELU gate (bf16 in/out)
    dwconv_ffn_gate<<<NPIX, 512>>>(p_upre, w_ffn_dw, p_ug);
    // 11. out = x1 + ug @ w_out (K=512 padded)
    gemm_bf16<<<dim3(CDIM / 64, NPIX / 128, 1), 256>>>(p_ug, UGLD, p_wout, CDIM, 0, p_x1,
                                                       out, 0, NPIX, UGLD, CDIM);
    (void)in_sizes; (void)n_in; (void)out_size;
}

// round 10
// speedup vs baseline: 1.6954x; 1.4092x over previous
#include <cuda_runtime.h>
#include <cuda_bf16.h>
#include <math.h>

#define NPIX   131072
#define BATCH  8
#define HH     128
#define WW     128
#define CDIM   192
#define C3     576
#define HEADS  6
#define HD     32
#define HID    510
#define HID2   1020
#define UPLD   1024       // padded M for FFN-in GEMM output
#define UGLD   512        // padded lda for gated ffn activation
#define NPB    16384

// ---------------- scratch (device globals) ----------------
__device__ __align__(128) __nv_bfloat16 g_y[(size_t)NPIX * CDIM];
__device__ __align__(128) __nv_bfloat16 g_qkv_pre[(size_t)NPIX * C3];
__device__ __align__(128) __nv_bfloat16 g_qkn[(size_t)NPIX * 384];   // normalized q,k (bf16)
__device__ __align__(128) __nv_bfloat16 g_v[(size_t)NPIX * CDIM];
__device__ __align__(128) float g_part[48 * 64 * 1024];
__device__ __align__(128) float g_attn[48 * 1024];
__device__ __align__(128) __nv_bfloat16 g_W2[BATCH * CDIM * CDIM];
__device__ __align__(128) float g_x1[(size_t)NPIX * CDIM];
__device__ __align__(128) __nv_bfloat16 g_upre[(size_t)NPIX * UPLD];
__device__ __align__(128) __nv_bfloat16 g_ug[(size_t)NPIX * UGLD];
// bf16 weights (padded)
__device__ __align__(128) __nv_bfloat16 g_wqkv[CDIM * C3];
__device__ __align__(128) __nv_bfloat16 g_win[CDIM * UPLD];     // cols 1020..1023 zero
__device__ __align__(128) __nv_bfloat16 g_wout[UGLD * CDIM];    // rows 510,511 zero

// ---------------- asm helpers ----------------
__device__ __forceinline__ void ldsm4(unsigned* r, unsigned addr) {
    asm volatile("ldmatrix.sync.aligned.m8n8.x4.shared.b16 {%0,%1,%2,%3}, [%4];"
                 : "=r"(r[0]), "=r"(r[1]), "=r"(r[2]), "=r"(r[3]) : "r"(addr));
}
__device__ __forceinline__ void ldsm4t(unsigned* r, unsigned addr) {
    asm volatile("ldmatrix.sync.aligned.m8n8.x4.trans.shared.b16 {%0,%1,%2,%3}, [%4];"
                 : "=r"(r[0]), "=r"(r[1]), "=r"(r[2]), "=r"(r[3]) : "r"(addr));
}
__device__ __forceinline__ void mma_bf16(float* d, const unsigned* a, unsigned b0, unsigned b1) {
    asm volatile(
        "mma.sync.aligned.m16n8k16.row.col.f32.bf16.bf16.f32 "
        "{%0,%1,%2,%3},{%4,%5,%6,%7},{%8,%9},{%0,%1,%2,%3};"
        : "+f"(d[0]), "+f"(d[1]), "+f"(d[2]), "+f"(d[3])
        : "r"(a[0]), "r"(a[1]), "r"(a[2]), "r"(a[3]), "r"(b0), "r"(b1));
}
__device__ __forceinline__ void cp16(unsigned dst, const void* src) {
    asm volatile("cp.async.cg.shared.global [%0], [%1], 16;" :: "r"(dst), "l"(src));
}
__device__ __forceinline__ void cp_commit() { asm volatile("cp.async.commit_group;"); }
__device__ __forceinline__ void cp_wait1() { asm volatile("cp.async.wait_group 1;"); }
__device__ __forceinline__ void cp_wait0() { asm volatile("cp.async.wait_group 0;"); }

// ---------------- weight convert + pad ----------------
__global__ void cvt_pad(const float* __restrict__ src, int srows, int scols,
                        __nv_bfloat16* __restrict__ dst, int dcols) {
    size_t i = (size_t)blockIdx.x * 256 + threadIdx.x;
    int r = (int)(i / dcols), cc = (int)(i % dcols);
    float v = (cc < scols) ? src[(size_t)r * scols + cc] : 0.f;
    dst[i] = __float2bfloat16(v);
}
__global__ void cvt_pad_rows(const float* __restrict__ src, int srows, int cols,
                             __nv_bfloat16* __restrict__ dst) {
    size_t i = (size_t)blockIdx.x * 256 + threadIdx.x;
    int r = (int)(i / cols), cc = (int)(i % cols);
    float v = (r < srows) ? src[(size_t)r * cols + cc] : 0.f;
    dst[i] = __float2bfloat16(v);
}

// ---------------- LayerNorm -> bf16 output ----------------
__global__ void ln_kernel(const float* __restrict__ x, const float* __restrict__ g,
                          const float* __restrict__ b, __nv_bfloat16* __restrict__ y) {
    size_t warp = ((size_t)blockIdx.x * blockDim.x + threadIdx.x) >> 5;
    int lane = threadIdx.x & 31;
    const float* xr = x + warp * CDIM;
    float v[6]; float s = 0.f, s2 = 0.f;
#pragma unroll
    for (int i = 0; i < 6; i++) { v[i] = xr[lane + 32 * i]; s += v[i]; s2 += v[i] * v[i]; }
#pragma unroll
    for (int o = 16; o; o >>= 1) {
        s  += __shfl_xor_sync(0xffffffffu, s, o);
        s2 += __shfl_xor_sync(0xffffffffu, s2, o);
    }
    float mu  = s * (1.f / CDIM);
    float var = s2 * (1.f / CDIM) - mu * mu;
    float rs = rsqrtf(var + 1e-3f);
    __nv_bfloat16* yr = y + warp * CDIM;
#pragma unroll
    for (int i = 0; i < 6; i++) {
        int c = lane + 32 * i;
        yr[c] = __float2bfloat16((v[i] - mu) * rs * g[c] + b[c]);
    }
}

// ---------------- bf16 GEMM, cp.async 3-stage: C = A*B (+R) ----------------
#define LDAK 40
#define LDBN 72
#define ASZE (128 * LDAK)
#define BSZE (32 * LDBN)
__global__ void __launch_bounds__(256) gemm_bf16(
    const __nv_bfloat16* __restrict__ A, int lda,
    const __nv_bfloat16* __restrict__ B, int ldb, long long bstride,
    const float* __restrict__ R,
    void* __restrict__ Cout, int obf16,
    int Nper, int K, int M)
{
    __shared__ __nv_bfloat16 As[3 * ASZE];
    __shared__ __nv_bfloat16 Bs[3 * BSZE];

    int bz = blockIdx.z;
    A += (size_t)bz * Nper * lda;
    B += (size_t)bz * bstride;
    size_t cbase = (size_t)bz * Nper * M;
    if (R) R += cbase;

    int tid = threadIdx.x;
    int row0 = blockIdx.y * 128;
    int col0 = blockIdx.x * 64;
    int warp = tid >> 5, lane = tid & 31;
    int wm = warp & 3, wn = warp >> 2;
    int g = lane >> 2, tig = lane & 3;
    int lrow = lane & 15, lhi = lane >> 4;

    unsigned as_u = (unsigned)__cvta_generic_to_shared(As);
    unsigned bs_u = (unsigned)__cvta_generic_to_shared(Bs);

    int ar0 = tid >> 2, ak0 = (tid & 3) << 3;
    int ar1 = (tid + 256) >> 2, ak1 = ((tid + 256) & 3) << 3;
    int bkr = tid >> 3, bnc = (tid & 7) << 3;

    float acc[2][4][4];
#pragma unroll
    for (int mt = 0; mt < 2; mt++)
#pragma unroll
        for (int nt = 0; nt < 4; nt++)
#pragma unroll
            for (int i = 0; i < 4; i++) acc[mt][nt][i] = 0.f;

    auto issue = [&](int s, int k0) {
        unsigned ab = as_u + s * (ASZE * 2);
        unsigned bb = bs_u + s * (BSZE * 2);
        cp16(ab + (ar0 * LDAK + ak0) * 2, A + (size_t)(row0 + ar0) * lda + k0 + ak0);
        cp16(ab + (ar1 * LDAK + ak1) * 2, A + (size_t)(row0 + ar1) * lda + k0 + ak1);
        cp16(bb + (bkr * LDBN + bnc) * 2, B + (size_t)(k0 + bkr) * ldb + col0 + bnc);
        cp_commit();
    };
    auto compute = [&](int s) {
        unsigned ab = as_u + s * (ASZE * 2);
        unsigned bb = bs_u + s * (BSZE * 2);
#pragma unroll
        for (int ks = 0; ks < 2; ks++) {
            unsigned afr[2][4];
#pragma unroll
            for (int mt = 0; mt < 2; mt++)
                ldsm4(afr[mt], ab + ((wm * 32 + mt * 16 + lrow) * LDAK + ks * 16 + lhi * 8) * 2);
            unsigned bfr[2][4];
#pragma unroll
            for (int np = 0; np < 2; np++)
                ldsm4t(bfr[np], bb + ((ks * 16 + lrow) * LDBN + wn * 32 + np * 16 + lhi * 8) * 2);
#pragma unroll
            for (int mt = 0; mt < 2; mt++)
#pragma unroll
                for (int np = 0; np < 2; np++) {
                    mma_bf16(acc[mt][np * 2 + 0], afr[mt], bfr[np][0], bfr[np][1]);
                    mma_bf16(acc[mt][np * 2 + 1], afr[mt], bfr[np][2], bfr[np][3]);
                }
        }
    };

    int kt = K >> 5;
    issue(0, 0);
    issue(1, 32);
    for (int it = 0; it < kt; it++) {
        if (it + 2 < kt) cp_wait1(); else cp_wait0();
        __syncthreads();
        if (it + 2 < kt) issue((it + 2) % 3, (it + 2) * 32);
        compute(it % 3);
    }

#pragma unroll
    for (int mt = 0; mt < 2; mt++) {
        size_t r = (size_t)row0 + wm * 32 + mt * 16 + g;
#pragma unroll
        for (int nt = 0; nt < 4; nt++) {
            int col = col0 + wn * 32 + nt * 8 + tig * 2;
            if (obf16) {
                __nv_bfloat16* C = (__nv_bfloat16*)Cout + cbase;
                *reinterpret_cast<__nv_bfloat162*>(C + r * M + col) =
                    __floats2bfloat162_rn(acc[mt][nt][0], acc[mt][nt][1]);
                *reinterpret_cast<__nv_bfloat162*>(C + (r + 8) * M + col) =
                    __floats2bfloat162_rn(acc[mt][nt][2], acc[mt][nt][3]);
            } else {
                float* C = (float*)Cout + cbase;
                float2 o0 = make_float2(acc[mt][nt][0], acc[mt][nt][1]);
                float2 o1 = make_float2(acc[mt][nt][2], acc[mt][nt][3]);
                if (R) {
                    float2 r0 = *reinterpret_cast<const float2*>(R + r * M + col);
                    float2 r1 = *reinterpret_cast<const float2*>(R + (r + 8) * M + col);
                    o0.x += r0.x; o0.y += r0.y; o1.x += r1.x; o1.y += r1.y;
                }
                *reinterpret_cast<float2*>(C + r * M + col) = o0;
                *reinterpret_cast<float2*>(C + (r + 8) * M + col) = o1;
            }
        }
    }
}

// ---------------- qkv dwconv (bf16 in) + q/k normalization -> bf16 qkn, bf16 v ----------
// 288 threads, each owns a channel PAIR (channels 2t, 2t+1).
__global__ void dwconv_qkv(const __nv_bfloat16* __restrict__ in, const float* __restrict__ w,
                           const float* __restrict__ mq, const float* __restrict__ vq,
                           const float* __restrict__ mk, const float* __restrict__ vk,
                           __nv_bfloat16* __restrict__ qkn, __nv_bfloat16* __restrict__ v) {
    int p = blockIdx.x;
    int c2 = threadIdx.x;    // 0..287
    int b = p >> 14, hw = p & 16383, yy = hw >> 7, xx = hw & 127;
    float a0 = 0.f, a1 = 0.f;
#pragma unroll
    for (int ky = -1; ky <= 1; ky++) {
        int yn = yy + ky;
        if ((unsigned)yn >= HH) continue;
#pragma unroll
        for (int kx = -1; kx <= 1; kx++) {
            int xn = xx + kx;
            if ((unsigned)xn >= WW) continue;
            size_t pix = (size_t)(b << 14) + (yn << 7) + xn;
            __nv_bfloat162 val = reinterpret_cast<const __nv_bfloat162*>(in + pix * C3)[c2];
            float2 wv = *reinterpret_cast<const float2*>(
                w + ((ky + 1) * 3 + (kx + 1)) * C3 + c2 * 2);
            a0 += __low2float(val) * wv.x;
            a1 += __high2float(val) * wv.y;
        }
    }
    if (c2 < 96) {
        float m = mq[hw], rs = rsqrtf(vq[hw]);
        reinterpret_cast<__nv_bfloat162*>(qkn + (size_t)p * 384)[c2] =
            __floats2bfloat162_rn((a0 - m) * rs, (a1 - m) * rs);
    } else if (c2 < 192) {
        float m = mk[hw], rs = rsqrtf(vk[hw]);
        reinterpret_cast<__nv_bfloat162*>(qkn + (size_t)p * 384)[c2] =
            __floats2bfloat162_rn((a0 - m) * rs, (a1 - m) * rs);
    } else {
        reinterpret_cast<__nv_bfloat162*>(v + (size_t)p * CDIM)[c2 - 192] =
            __floats2bfloat162_rn(a0, a1);
    }
}

// ---------------- FFN dwconv + GELU gate (bf162 vectorized, 256 threads) ----------------
__global__ void dwconv_ffn_gate(const __nv_bfloat16* __restrict__ in,
                                const float* __restrict__ w,
                                __nv_bfloat16* __restrict__ out) {
    int p = blockIdx.x;
    int i = threadIdx.x;          // 0..255; pairs of u-channels
    if (i >= 255) {               // zero-pad cols 510,511
        reinterpret_cast<__nv_bfloat162*>(out + (size_t)p * UGLD)[255] =
            __floats2bfloat162_rn(0.f, 0.f);
        return;
    }
    int b = p >> 14, hw = p & 16383, yy = hw >> 7, xx = hw & 127;
    int c = i * 2;
    float a10 = 0.f, a11 = 0.f, a20 = 0.f, a21 = 0.f;
#pragma unroll
    for (int ky = -1; ky <= 1; ky++) {
        int yn = yy + ky;
        if ((unsigned)yn >= HH) continue;
#pragma unroll
        for (int kx = -1; kx <= 1; kx++) {
            int xn = xx + kx;
            if ((unsigned)xn >= WW) continue;
            size_t idx = ((size_t)(b << 14) + (yn << 7) + xn) * UPLD;
            int wi = ((ky + 1) * 3 + (kx + 1)) * HID2;
            __nv_bfloat162 v1 = *reinterpret_cast<const __nv_bfloat162*>(in + idx + c);
            __nv_bfloat162 v2 = *reinterpret_cast<const __nv_bfloat162*>(in + idx + HID + c);
            float2 w1 = *reinterpret_cast<const float2*>(w + wi + c);
            float2 w2 = *reinterpret_cast<const float2*>(w + wi + HID + c);
            a10 += __low2float(v1) * w1.x;  a11 += __high2float(v1) * w1.y;
            a20 += __low2float(v2) * w2.x;  a21 += __high2float(v2) * w2.y;
        }
    }
    float gl0 = 0.5f * a10 * (1.f + erff(a10 * 0.70710678118654752f));
    float gl1 = 0.5f * a11 * (1.f + erff(a11 * 0.70710678118654752f));
    reinterpret_cast<__nv_bfloat162*>(out + (size_t)p * UGLD)[i] =
        __floats2bfloat162_rn(gl0 * a20, gl1 * a21);
}

// ---------------- attention K^T Q partials (bf16 input, fp32 smem + FFMA) ----------------
__global__ void __launch_bounds__(256) attn_partial(
        const __nv_bfloat16* __restrict__ qkn, float* __restrict__ part) {
    int chunk = blockIdx.x, h = blockIdx.y, b = blockIdx.z;
    __shared__ __align__(16) float sq[2][16][32];
    __shared__ __align__(16) float sk[2][16][32];
    int tid = threadIdx.x;
    int sub = tid >> 7;
    int slot = tid & 127;
    int c0 = (slot >> 3) << 1;
    int d0 = (slot & 7) << 2;
    size_t rowbase = ((size_t)b * NPB + chunk * 512 + sub * 256) * 384;
    float a0[4] = {}, a1[4] = {};

    for (int n0 = 0; n0 < 256; n0 += 16) {
#pragma unroll
        for (int j = 0; j < 2; j++) {
            int sid = slot + j * 128;
            int nn = sid >> 4;
            int prt = sid & 15;
            const __nv_bfloat16* src = qkn + rowbase + (size_t)(n0 + nn) * 384 +
                                       ((prt & 8) ? 192 : 0) + h * HD + (prt & 7) * 4;
            uint2 raw = *reinterpret_cast<const uint2*>(src);
            __nv_bfloat162 p0 = *reinterpret_cast<const __nv_bfloat162*>(&raw.x);
            __nv_bfloat162 p1 = *reinterpret_cast<const __nv_bfloat162*>(&raw.y);
            float* dst = (prt & 8) ? &sk[sub][nn][(prt & 7) * 4]
                                   : &sq[sub][nn][(prt & 7) * 4];
            *reinterpret_cast<float4*>(dst) = make_float4(
                __low2float(p0), __high2float(p0), __low2float(p1), __high2float(p1));
        }
        __syncthreads();
#pragma unroll
        for (int nn = 0; nn < 16; nn++) {
            float kv0 = sk[sub][nn][c0];
            float kv1 = sk[sub][nn][c0 + 1];
            float4 qv = *reinterpret_cast<const float4*>(&sq[sub][nn][d0]);
            a0[0] += kv0 * qv.x; a0[1] += kv0 * qv.y; a0[2] += kv0 * qv.z; a0[3] += kv0 * qv.w;
            a1[0] += kv1 * qv.x; a1[1] += kv1 * qv.y; a1[2] += kv1 * qv.z; a1[3] += kv1 * qv.w;
        }
        __syncthreads();
    }
    float* o = part + ((size_t)(b * HEADS + h) * 64 + chunk * 2 + sub) * 1024;
    *reinterpret_cast<float4*>(&o[c0 * 32 + d0])       = make_float4(a0[0], a0[1], a0[2], a0[3]);
    *reinterpret_cast<float4*>(&o[(c0 + 1) * 32 + d0]) = make_float4(a1[0], a1[1], a1[2], a1[3]);
}

// ---------------- reduce partials + temp + softmax over axis c ----------------
__global__ void softmax_kernel(const float* __restrict__ part, const float* __restrict__ temp,
                               float* __restrict__ attn) {
    int bh = blockIdx.x;
    int h = bh % HEADS;
    int d = threadIdx.x;
    float t = temp[h];
    float v[32];
#pragma unroll
    for (int c = 0; c < 32; c++) {
        float s = 0.f;
        for (int ch = 0; ch < 64; ch++)
            s += part[((size_t)bh * 64 + ch) * 1024 + c * 32 + d];
        v[c] = s * t;
    }
    float m = -1e30f;
#pragma unroll
    for (int c = 0; c < 32; c++) m = fmaxf(m, v[c]);
    float sum = 0.f;
#pragma unroll
    for (int c = 0; c < 32; c++) { v[c] = expf(v[c] - m); sum += v[c]; }
    float inv = 1.f / sum;
#pragma unroll
    for (int c = 0; c < 32; c++)
        attn[(size_t)bh * 1024 + c * 32 + d] = v[c] * inv;
}

// ---------------- fold attn into w_proj -> bf16 W2 ----------------
__global__ void w2_kernel(const float* __restrict__ attn, const float* __restrict__ wproj,
                          __nv_bfloat16* __restrict__ W2) {
    int bh = blockIdx.x;
    int b = bh / HEADS, h = bh % HEADS;
    __shared__ float sA[32][32];
    __shared__ float sW[32][192];
    int tid = threadIdx.x;          // 192
    for (int t = tid; t < 1024; t += 192)
        sA[t >> 5][t & 31] = attn[(size_t)bh * 1024 + t];
    for (int dd = 0; dd < 32; dd++)
        sW[dd][tid] = wproj[(h * HD + dd) * CDIM + tid];
    __syncthreads();
    int o = tid;
    for (int c = 0; c < 32; c++) {
        float acc = 0.f;
#pragma unroll
        for (int dd = 0; dd < 32; dd++) acc += sA[c][dd] * sW[dd][o];
        W2[((size_t)b * CDIM + h * HD + c) * CDIM + o] = __float2bfloat16(acc);
    }
}

// ---------------- launch ----------------
extern "C" void kernel_launch(void* const* d_in, const int* in_sizes, int n_in,
                              void* d_out, int out_size) {
    const float* x       = (const float*)d_in[0];
    const float* g1      = (const float*)d_in[1];
    const float* b1      = (const float*)d_in[2];
    const float* w_qkv   = (const float*)d_in[3];
    const float* w_qkv_dw= (const float*)d_in[4];
    const float* temp    = (const float*)d_in[5];
    const float* mean_q  = (const float*)d_in[6];
    const float* var_q   = (const float*)d_in[7];
    const float* mean_k  = (const float*)d_in[8];
    const float* var_k   = (const float*)d_in[9];
    const float* w_proj  = (const float*)d_in[10];
    const float* g2      = (const float*)d_in[11];
    const float* b2      = (const float*)d_in[12];
    const float* w_in    = (const float*)d_in[13];
    const float* w_ffn_dw= (const float*)d_in[14];
    const float* w_out   = (const float*)d_in[15];
    float* out = (float*)d_out;

    __nv_bfloat16 *p_y, *p_qkvp, *p_qkn, *p_v, *p_W2, *p_upre, *p_ug, *p_wqkv, *p_win, *p_wout;
    float *p_part, *p_attn, *p_x1;
    cudaGetSymbolAddress((void**)&p_y,    g_y);
    cudaGetSymbolAddress((void**)&p_qkvp, g_qkv_pre);
    cudaGetSymbolAddress((void**)&p_qkn,  g_qkn);
    cudaGetSymbolAddress((void**)&p_v,    g_v);
    cudaGetSymbolAddress((void**)&p_part, g_part);
    cudaGetSymbolAddress((void**)&p_attn, g_attn);
    cudaGetSymbolAddress((void**)&p_W2,   g_W2);
    cudaGetSymbolAddress((void**)&p_x1,   g_x1);
    cudaGetSymbolAddress((void**)&p_upre, g_upre);
    cudaGetSymbolAddress((void**)&p_ug,   g_ug);
    cudaGetSymbolAddress((void**)&p_wqkv, g_wqkv);
    cudaGetSymbolAddress((void**)&p_win,  g_win);
    cudaGetSymbolAddress((void**)&p_wout, g_wout);

    // 0. weight conversion (bf16, padded)
    cvt_pad<<<(CDIM * C3) / 256, 256>>>(w_qkv, CDIM, C3, p_wqkv, C3);
    cvt_pad<<<(CDIM * UPLD) / 256, 256>>>(w_in, CDIM, HID2, p_win, UPLD);
    cvt_pad_rows<<<(UGLD * CDIM) / 256, 256>>>(w_out, HID, CDIM, p_wout);

    // 1. LN1 -> bf16
    ln_kernel<<<NPIX / 8, 256>>>(x, g1, b1, p_y);
    // 2. qkv = y @ w_qkv -> bf16
    gemm_bf16<<<dim3(C3 / 64, NPIX / 128, 1), 256>>>(p_y, CDIM, p_wqkv, C3, 0, nullptr,
                                                     p_qkvp, 1, NPIX, CDIM, C3);
    // 3. dwconv 3x3 + q/k normalization (bf16 qkn) + v bf16
    dwconv_qkv<<<NPIX, 288>>>(p_qkvp, w_qkv_dw, mean_q, var_q, mean_k, var_k, p_qkn, p_v);
    // 4. K^T Q partials
    attn_partial<<<dim3(32, HEADS, BATCH), 256>>>(p_qkn, p_part);
    // 5. softmax(axis=-2)
    softmax_kernel<<<48, 32>>>(p_part, temp, p_attn);
    // 6. fold attn into w_proj -> bf16 W2
    w2_kernel<<<48, 192>>>(p_attn, w_proj, p_W2);
    // 7. x1 = x + V @ W2[b]
    gemm_bf16<<<dim3(CDIM / 64, NPB / 128, BATCH), 256>>>(p_v, CDIM, p_W2, CDIM,
                                                          (long long)CDIM * CDIM, x,
                                                          p_x1, 0, NPB, CDIM, CDIM);
    // 8. LN2 -> bf16
    ln_kernel<<<NPIX / 8, 256>>>(p_x1, g2, b2, p_y);
    // 9. u_pre = y @ w_in (bf16 out, padded M=1024)
    gemm_bf16<<<dim3(UPLD / 64, NPIX / 128, 1), 256>>>(p_y, CDIM, p_win, UPLD, 0, nullptr,
                                                       p_upre, 1, NPIX, CDIM, UPLD);
    // 10. dwconv + GELU gate (bf162 vectorized)
    dwconv_ffn_gate<<<NPIX, 256>>>(p_upre, w_ffn_dw, p_ug);
    // 11. out = x1 + ug @ w_out (K=512 padded)
    gemm_bf16<<<dim3(CDIM / 64, NPIX / 128, 1), 256>>>(p_ug, UGLD, p_wout, CDIM, 0, p_x1,
                                                       out, 0, NPIX, UGLD, CDIM);
    (void)in_sizes; (void)n_in; (void)out_size;
}

// round 13
// speedup vs baseline: 1.7752x; 1.0471x over previous
#include <cuda_runtime.h>
#include <cuda_bf16.h>
#include <math.h>

#define NPIX   131072
#define BATCH  8
#define HH     128
#define WW     128
#define CDIM   192
#define C3     576
#define HEADS  6
#define HD     32
#define HID    510
#define HID2   1020
#define UPLD   1024       // padded M for FFN-in GEMM output
#define UGLD   512        // padded lda for gated ffn activation
#define NPB    16384

// ---------------- scratch (device globals) ----------------
__device__ __align__(128) __nv_bfloat16 g_y[(size_t)NPIX * CDIM];
__device__ __align__(128) __nv_bfloat16 g_qkv_pre[(size_t)NPIX * C3];
__device__ __align__(128) __nv_bfloat16 g_qkn[(size_t)NPIX * 384];   // normalized q,k (bf16)
__device__ __align__(128) __nv_bfloat16 g_v[(size_t)NPIX * CDIM];
__device__ __align__(128) float g_part[48 * 32 * 1024];
__device__ __align__(128) float g_attn[48 * 1024];
__device__ __align__(128) __nv_bfloat16 g_W2[BATCH * CDIM * CDIM];
__device__ __align__(128) float g_x1[(size_t)NPIX * CDIM];
__device__ __align__(128) __nv_bfloat16 g_upre[(size_t)NPIX * UPLD];
__device__ __align__(128) __nv_bfloat16 g_ug[(size_t)NPIX * UGLD];
// bf16 weights (padded)
__device__ __align__(128) __nv_bfloat16 g_wqkv[CDIM * C3];
__device__ __align__(128) __nv_bfloat16 g_win[CDIM * UPLD];     // cols 1020..1023 zero
__device__ __align__(128) __nv_bfloat16 g_wout[UGLD * CDIM];    // rows 510,511 zero

// ---------------- asm helpers ----------------
__device__ __forceinline__ void ldsm4(unsigned* r, unsigned addr) {
    asm volatile("ldmatrix.sync.aligned.m8n8.x4.shared.b16 {%0,%1,%2,%3}, [%4];"
                 : "=r"(r[0]), "=r"(r[1]), "=r"(r[2]), "=r"(r[3]) : "r"(addr));
}
__device__ __forceinline__ void ldsm4t(unsigned* r, unsigned addr) {
    asm volatile("ldmatrix.sync.aligned.m8n8.x4.trans.shared.b16 {%0,%1,%2,%3}, [%4];"
                 : "=r"(r[0]), "=r"(r[1]), "=r"(r[2]), "=r"(r[3]) : "r"(addr));
}
__device__ __forceinline__ void mma_bf16(float* d, const unsigned* a, unsigned b0, unsigned b1) {
    asm volatile(
        "mma.sync.aligned.m16n8k16.row.col.f32.bf16.bf16.f32 "
        "{%0,%1,%2,%3},{%4,%5,%6,%7},{%8,%9},{%0,%1,%2,%3};"
        : "+f"(d[0]), "+f"(d[1]), "+f"(d[2]), "+f"(d[3])
        : "r"(a[0]), "r"(a[1]), "r"(a[2]), "r"(a[3]), "r"(b0), "r"(b1));
}
__device__ __forceinline__ void cp16(unsigned dst, const void* src) {
    asm volatile("cp.async.cg.shared.global [%0], [%1], 16;" :: "r"(dst), "l"(src));
}
__device__ __forceinline__ void cp_commit() { asm volatile("cp.async.commit_group;"); }
__device__ __forceinline__ void cp_wait1() { asm volatile("cp.async.wait_group 1;"); }
__device__ __forceinline__ void cp_wait0() { asm volatile("cp.async.wait_group 0;"); }

// ---------------- weight convert + pad ----------------
__global__ void cvt_pad(const float* __restrict__ src, int srows, int scols,
                        __nv_bfloat16* __restrict__ dst, int dcols) {
    size_t i = (size_t)blockIdx.x * 256 + threadIdx.x;
    int r = (int)(i / dcols), cc = (int)(i % dcols);
    float v = (cc < scols) ? src[(size_t)r * scols + cc] : 0.f;
    dst[i] = __float2bfloat16(v);
}
__global__ void cvt_pad_rows(const float* __restrict__ src, int srows, int cols,
                             __nv_bfloat16* __restrict__ dst) {
    size_t i = (size_t)blockIdx.x * 256 + threadIdx.x;
    int r = (int)(i / cols), cc = (int)(i % cols);
    float v = (r < srows) ? src[(size_t)r * cols + cc] : 0.f;
    dst[i] = __float2bfloat16(v);
}

// ---------------- LayerNorm -> bf16 output ----------------
__global__ void ln_kernel(const float* __restrict__ x, const float* __restrict__ g,
                          const float* __restrict__ b, __nv_bfloat16* __restrict__ y) {
    size_t warp = ((size_t)blockIdx.x * blockDim.x + threadIdx.x) >> 5;
    int lane = threadIdx.x & 31;
    const float* xr = x + warp * CDIM;
    float v[6]; float s = 0.f, s2 = 0.f;
#pragma unroll
    for (int i = 0; i < 6; i++) { v[i] = xr[lane + 32 * i]; s += v[i]; s2 += v[i] * v[i]; }
#pragma unroll
    for (int o = 16; o; o >>= 1) {
        s  += __shfl_xor_sync(0xffffffffu, s, o);
        s2 += __shfl_xor_sync(0xffffffffu, s2, o);
    }
    float mu  = s * (1.f / CDIM);
    float var = s2 * (1.f / CDIM) - mu * mu;
    float rs = rsqrtf(var + 1e-3f);
    __nv_bfloat16* yr = y + warp * CDIM;
#pragma unroll
    for (int i = 0; i < 6; i++) {
        int c = lane + 32 * i;
        yr[c] = __float2bfloat16((v[i] - mu) * rs * g[c] + b[c]);
    }
}

// ---------------- bf16 GEMM 128x64 tile, cp.async 3-stage: C = A*B (+R) ----------------
#define LDAK 40
#define LDBN 72
#define ASZE (128 * LDAK)
#define BSZE (32 * LDBN)
__global__ void __launch_bounds__(256) gemm_bf16(
    const __nv_bfloat16* __restrict__ A, int lda,
    const __nv_bfloat16* __restrict__ B, int ldb, long long bstride,
    const float* __restrict__ R,
    void* __restrict__ Cout, int obf16,
    int Nper, int K, int M)
{
    __shared__ __nv_bfloat16 As[3 * ASZE];
    __shared__ __nv_bfloat16 Bs[3 * BSZE];

    int bz = blockIdx.z;
    A += (size_t)bz * Nper * lda;
    B += (size_t)bz * bstride;
    size_t cbase = (size_t)bz * Nper * M;
    if (R) R += cbase;

    int tid = threadIdx.x;
    int row0 = blockIdx.y * 128;
    int col0 = blockIdx.x * 64;
    int warp = tid >> 5, lane = tid & 31;
    int wm = warp & 3, wn = warp >> 2;
    int g = lane >> 2, tig = lane & 3;
    int lrow = lane & 15, lhi = lane >> 4;

    unsigned as_u = (unsigned)__cvta_generic_to_shared(As);
    unsigned bs_u = (unsigned)__cvta_generic_to_shared(Bs);

    int ar0 = tid >> 2, ak0 = (tid & 3) << 3;
    int ar1 = (tid + 256) >> 2, ak1 = ((tid + 256) & 3) << 3;
    int bkr = tid >> 3, bnc = (tid & 7) << 3;

    float acc[2][4][4];
#pragma unroll
    for (int mt = 0; mt < 2; mt++)
#pragma unroll
        for (int nt = 0; nt < 4; nt++)
#pragma unroll
            for (int i = 0; i < 4; i++) acc[mt][nt][i] = 0.f;

    auto issue = [&](int s, int k0) {
        unsigned ab = as_u + s * (ASZE * 2);
        unsigned bb = bs_u + s * (BSZE * 2);
        cp16(ab + (ar0 * LDAK + ak0) * 2, A + (size_t)(row0 + ar0) * lda + k0 + ak0);
        cp16(ab + (ar1 * LDAK + ak1) * 2, A + (size_t)(row0 + ar1) * lda + k0 + ak1);
        cp16(bb + (bkr * LDBN + bnc) * 2, B + (size_t)(k0 + bkr) * ldb + col0 + bnc);
        cp_commit();
    };
    auto compute = [&](int s) {
        unsigned ab = as_u + s * (ASZE * 2);
        unsigned bb = bs_u + s * (BSZE * 2);
#pragma unroll
        for (int ks = 0; ks < 2; ks++) {
            unsigned afr[2][4];
#pragma unroll
            for (int mt = 0; mt < 2; mt++)
                ldsm4(afr[mt], ab + ((wm * 32 + mt * 16 + lrow) * LDAK + ks * 16 + lhi * 8) * 2);
            unsigned bfr[2][4];
#pragma unroll
            for (int np = 0; np < 2; np++)
                ldsm4t(bfr[np], bb + ((ks * 16 + lrow) * LDBN + wn * 32 + np * 16 + lhi * 8) * 2);
#pragma unroll
            for (int mt = 0; mt < 2; mt++)
#pragma unroll
                for (int np = 0; np < 2; np++) {
                    mma_bf16(acc[mt][np * 2 + 0], afr[mt], bfr[np][0], bfr[np][1]);
                    mma_bf16(acc[mt][np * 2 + 1], afr[mt], bfr[np][2], bfr[np][3]);
                }
        }
    };

    int kt = K >> 5;
    issue(0, 0);
    issue(1, 32);
    for (int it = 0; it < kt; it++) {
        if (it + 2 < kt) cp_wait1(); else cp_wait0();
        __syncthreads();
        if (it + 2 < kt) issue((it + 2) % 3, (it + 2) * 32);
        compute(it % 3);
    }

#pragma unroll
    for (int mt = 0; mt < 2; mt++) {
        size_t r = (size_t)row0 + wm * 32 + mt * 16 + g;
#pragma unroll
        for (int nt = 0; nt < 4; nt++) {
            int col = col0 + wn * 32 + nt * 8 + tig * 2;
            if (obf16) {
                __nv_bfloat16* C = (__nv_bfloat16*)Cout + cbase;
                *reinterpret_cast<__nv_bfloat162*>(C + r * M + col) =
                    __floats2bfloat162_rn(acc[mt][nt][0], acc[mt][nt][1]);
                *reinterpret_cast<__nv_bfloat162*>(C + (r + 8) * M + col) =
                    __floats2bfloat162_rn(acc[mt][nt][2], acc[mt][nt][3]);
            } else {
                float* C = (float*)Cout + cbase;
                float2 o0 = make_float2(acc[mt][nt][0], acc[mt][nt][1]);
                float2 o1 = make_float2(acc[mt][nt][2], acc[mt][nt][3]);
                if (R) {
                    float2 r0 = *reinterpret_cast<const float2*>(R + r * M + col);
                    float2 r1 = *reinterpret_cast<const float2*>(R + (r + 8) * M + col);
                    o0.x += r0.x; o0.y += r0.y; o1.x += r1.x; o1.y += r1.y;
                }
                *reinterpret_cast<float2*>(C + r * M + col) = o0;
                *reinterpret_cast<float2*>(C + (r + 8) * M + col) = o1;
            }
        }
    }
}

// ---------------- bf16 GEMM 128x128 tile (dynamic smem), bf16 output, no residual ------
// LDB2 must keep row pitch (LDB2*2 bytes) a multiple of 16 for cp.async alignment.
#define LDB2 136
#define BSZ2 (32 * LDB2)
__global__ void __launch_bounds__(256) gemm_bf16_128(
    const __nv_bfloat16* __restrict__ A, int lda,
    const __nv_bfloat16* __restrict__ B, int ldb,
    __nv_bfloat16* __restrict__ C,
    int K, int M)
{
    extern __shared__ __nv_bfloat16 smem[];
    __nv_bfloat16* As = smem;               // 3 * ASZE
    __nv_bfloat16* Bs = smem + 3 * ASZE;    // 3 * BSZ2

    int tid = threadIdx.x;
    int row0 = blockIdx.y * 128;
    int col0 = blockIdx.x * 128;
    int warp = tid >> 5, lane = tid & 31;
    int wm = warp & 3, wn = warp >> 2;
    int g = lane >> 2, tig = lane & 3;
    int lrow = lane & 15, lhi = lane >> 4;

    unsigned as_u = (unsigned)__cvta_generic_to_shared(As);
    unsigned bs_u = (unsigned)__cvta_generic_to_shared(Bs);

    int ar0 = tid >> 2, ak0 = (tid & 3) << 3;
    int ar1 = (tid + 256) >> 2, ak1 = ((tid + 256) & 3) << 3;
    int bkr0 = tid >> 4, bnc0 = (tid & 15) << 3;
    int bkr1 = (tid + 256) >> 4, bnc1 = ((tid + 256) & 15) << 3;

    float acc[2][8][4];
#pragma unroll
    for (int mt = 0; mt < 2; mt++)
#pragma unroll
        for (int nt = 0; nt < 8; nt++)
#pragma unroll
            for (int i = 0; i < 4; i++) acc[mt][nt][i] = 0.f;

    auto issue = [&](int s, int k0) {
        unsigned ab = as_u + s * (ASZE * 2);
        unsigned bb = bs_u + s * (BSZ2 * 2);
        cp16(ab + (ar0 * LDAK + ak0) * 2, A + (size_t)(row0 + ar0) * lda + k0 + ak0);
        cp16(ab + (ar1 * LDAK + ak1) * 2, A + (size_t)(row0 + ar1) * lda + k0 + ak1);
        cp16(bb + (bkr0 * LDB2 + bnc0) * 2, B + (size_t)(k0 + bkr0) * ldb + col0 + bnc0);
        cp16(bb + (bkr1 * LDB2 + bnc1) * 2, B + (size_t)(k0 + bkr1) * ldb + col0 + bnc1);
        cp_commit();
    };
    auto compute = [&](int s) {
        unsigned ab = as_u + s * (ASZE * 2);
        unsigned bb = bs_u + s * (BSZ2 * 2);
#pragma unroll
        for (int ks = 0; ks < 2; ks++) {
            unsigned afr[2][4];
#pragma unroll
            for (int mt = 0; mt < 2; mt++)
                ldsm4(afr[mt], ab + ((wm * 32 + mt * 16 + lrow) * LDAK + ks * 16 + lhi * 8) * 2);
            unsigned bfr[4][4];
#pragma unroll
            for (int np = 0; np < 4; np++)
                ldsm4t(bfr[np], bb + ((ks * 16 + lrow) * LDB2 + wn * 64 + np * 16 + lhi * 8) * 2);
#pragma unroll
            for (int mt = 0; mt < 2; mt++)
#pragma unroll
                for (int np = 0; np < 4; np++) {
                    mma_bf16(acc[mt][np * 2 + 0], afr[mt], bfr[np][0], bfr[np][1]);
                    mma_bf16(acc[mt][np * 2 + 1], afr[mt], bfr[np][2], bfr[np][3]);
                }
        }
    };

    int kt = K >> 5;
    issue(0, 0);
    issue(1, 32);
    for (int it = 0; it < kt; it++) {
        if (it + 2 < kt) cp_wait1(); else cp_wait0();
        __syncthreads();
        if (it + 2 < kt) issue((it + 2) % 3, (it + 2) * 32);
        compute(it % 3);
    }

#pragma unroll
    for (int mt = 0; mt < 2; mt++) {
        size_t r = (size_t)row0 + wm * 32 + mt * 16 + g;
#pragma unroll
        for (int nt = 0; nt < 8; nt++) {
            int col = col0 + wn * 64 + nt * 8 + tig * 2;
            *reinterpret_cast<__nv_bfloat162*>(C + r * M + col) =
                __floats2bfloat162_rn(acc[mt][nt][0], acc[mt][nt][1]);
            *reinterpret_cast<__nv_bfloat162*>(C + (r + 8) * M + col) =
                __floats2bfloat162_rn(acc[mt][nt][2], acc[mt][nt][3]);
        }
    }
}

// ---------------- qkv dwconv (bf16 in) + q/k normalization -> bf16 qkn, bf16 v ----------
__global__ void dwconv_qkv(const __nv_bfloat16* __restrict__ in, const float* __restrict__ w,
                           const float* __restrict__ mq, const float* __restrict__ vq,
                           const float* __restrict__ mk, const float* __restrict__ vk,
                           __nv_bfloat16* __restrict__ qkn, __nv_bfloat16* __restrict__ v) {
    int p = blockIdx.x;
    int c2 = threadIdx.x;    // 0..287
    int b = p >> 14, hw = p & 16383, yy = hw >> 7, xx = hw & 127;
    float a0 = 0.f, a1 = 0.f;
#pragma unroll
    for (int ky = -1; ky <= 1; ky++) {
        int yn = yy + ky;
        if ((unsigned)yn >= HH) continue;
#pragma unroll
        for (int kx = -1; kx <= 1; kx++) {
            int xn = xx + kx;
            if ((unsigned)xn >= WW) continue;
            size_t pix = (size_t)(b << 14) + (yn << 7) + xn;
            __nv_bfloat162 val = reinterpret_cast<const __nv_bfloat162*>(in + pix * C3)[c2];
            float2 wv = *reinterpret_cast<const float2*>(
                w + ((ky + 1) * 3 + (kx + 1)) * C3 + c2 * 2);
            a0 += __low2float(val) * wv.x;
            a1 += __high2float(val) * wv.y;
        }
    }
    if (c2 < 96) {
        float m = mq[hw], rs = rsqrtf(vq[hw]);
        reinterpret_cast<__nv_bfloat162*>(qkn + (size_t)p * 384)[c2] =
            __floats2bfloat162_rn((a0 - m) * rs, (a1 - m) * rs);
    } else if (c2 < 192) {
        float m = mk[hw], rs = rsqrtf(vk[hw]);
        reinterpret_cast<__nv_bfloat162*>(qkn + (size_t)p * 384)[c2] =
            __floats2bfloat162_rn((a0 - m) * rs, (a1 - m) * rs);
    } else {
        reinterpret_cast<__nv_bfloat162*>(v + (size_t)p * CDIM)[c2 - 192] =
            __floats2bfloat162_rn(a0, a1);
    }
}

// ---------------- FFN dwconv + GELU gate (bf162 vectorized, 256 threads) ----------------
__global__ void dwconv_ffn_gate(const __nv_bfloat16* __restrict__ in,
                                const float* __restrict__ w,
                                __nv_bfloat16* __restrict__ out) {
    int p = blockIdx.x;
    int i = threadIdx.x;
    if (i >= 255) {
        reinterpret_cast<__nv_bfloat162*>(out + (size_t)p * UGLD)[255] =
            __floats2bfloat162_rn(0.f, 0.f);
        return;
    }
    int b = p >> 14, hw = p & 16383, yy = hw >> 7, xx = hw & 127;
    int c = i * 2;
    float a10 = 0.f, a11 = 0.f, a20 = 0.f, a21 = 0.f;
#pragma unroll
    for (int ky = -1; ky <= 1; ky++) {
        int yn = yy + ky;
        if ((unsigned)yn >= HH) continue;
#pragma unroll
        for (int kx = -1; kx <= 1; kx++) {
            int xn = xx + kx;
            if ((unsigned)xn >= WW) continue;
            size_t idx = ((size_t)(b << 14) + (yn << 7) + xn) * UPLD;
            int wi = ((ky + 1) * 3 + (kx + 1)) * HID2;
            __nv_bfloat162 v1 = *reinterpret_cast<const __nv_bfloat162*>(in + idx + c);
            __nv_bfloat162 v2 = *reinterpret_cast<const __nv_bfloat162*>(in + idx + HID + c);
            float2 w1 = *reinterpret_cast<const float2*>(w + wi + c);
            float2 w2 = *reinterpret_cast<const float2*>(w + wi + HID + c);
            a10 += __low2float(v1) * w1.x;  a11 += __high2float(v1) * w1.y;
            a20 += __low2float(v2) * w2.x;  a21 += __high2float(v2) * w2.y;
        }
    }
    float gl0 = 0.5f * a10 * (1.f + erff(a10 * 0.70710678118654752f));
    float gl1 = 0.5f * a11 * (1.f + erff(a11 * 0.70710678118654752f));
    reinterpret_cast<__nv_bfloat162*>(out + (size_t)p * UGLD)[i] =
        __floats2bfloat162_rn(gl0 * a20, gl1 * a21);
}

// ---------------- attention K^T Q partials via tensor cores ----------------
// grid (4, HEADS, BATCH), 256 threads = 8 warps; each warp owns 512 n-rows.
#define LDQ 40
#define LDKT 24
__global__ void __launch_bounds__(256) attn_partial(
        const __nv_bfloat16* __restrict__ qkn, float* __restrict__ part) {
    int chunk = blockIdx.x, h = blockIdx.y, b = blockIdx.z;
    __shared__ __nv_bfloat16 sq[8][16 * LDQ];
    __shared__ __nv_bfloat16 skt[8][32 * LDKT];
    int tid = threadIdx.x, warp = tid >> 5, lane = tid & 31;
    int lrow = lane & 15, lhi = lane >> 4;
    size_t rowbase = ((size_t)b * NPB + chunk * 4096 + warp * 512) * 384 + h * HD;
    unsigned squ = (unsigned)__cvta_generic_to_shared(sq[warp]);
    unsigned sktu = (unsigned)__cvta_generic_to_shared(skt[warp]);

    float acc[2][4][4];
#pragma unroll
    for (int mt = 0; mt < 2; mt++)
#pragma unroll
        for (int nt = 0; nt < 4; nt++)
#pragma unroll
            for (int i = 0; i < 4; i++) acc[mt][nt][i] = 0.f;

    for (int st = 0; st < 32; st++) {
#pragma unroll
        for (int i = 0; i < 8; i++) {
            int cch = lane + i * 32;          // 0..255
            int row = cch >> 4, prt = cch & 15;
            const __nv_bfloat16* src = qkn + rowbase + (size_t)(st * 16 + row) * 384 +
                                       ((prt & 8) ? (192 + (prt - 8) * 4) : prt * 4);
            uint2 raw = *reinterpret_cast<const uint2*>(src);
            if (prt < 8) {
                *reinterpret_cast<uint2*>(&sq[warp][row * LDQ + prt * 4]) = raw;
            } else {
                const __nv_bfloat16* pv = reinterpret_cast<const __nv_bfloat16*>(&raw);
                int c4 = (prt - 8) * 4;
                skt[warp][(c4 + 0) * LDKT + row] = pv[0];
                skt[warp][(c4 + 1) * LDKT + row] = pv[1];
                skt[warp][(c4 + 2) * LDKT + row] = pv[2];
                skt[warp][(c4 + 3) * LDKT + row] = pv[3];
            }
        }
        __syncwarp();
        unsigned afr[2][4], bfr[2][4];
#pragma unroll
        for (int mt = 0; mt < 2; mt++)
            ldsm4(afr[mt], sktu + ((mt * 16 + lrow) * LDKT + lhi * 8) * 2);
#pragma unroll
        for (int np = 0; np < 2; np++)
            ldsm4t(bfr[np], squ + (lrow * LDQ + np * 16 + lhi * 8) * 2);
#pragma unroll
        for (int mt = 0; mt < 2; mt++)
#pragma unroll
            for (int np = 0; np < 2; np++) {
                mma_bf16(acc[mt][np * 2 + 0], afr[mt], bfr[np][0], bfr[np][1]);
                mma_bf16(acc[mt][np * 2 + 1], afr[mt], bfr[np][2], bfr[np][3]);
            }
        __syncwarp();
    }
    int g = lane >> 2, tig = lane & 3;
    float* o = part + ((size_t)(b * HEADS + h) * 32 + chunk * 8 + warp) * 1024;
#pragma unroll
    for (int mt = 0; mt < 2; mt++)
#pragma unroll
        for (int nt = 0; nt < 4; nt++) {
            int r0 = mt * 16 + g, cc = nt * 8 + tig * 2;
            o[r0 * 32 + cc]           = acc[mt][nt][0];
            o[r0 * 32 + cc + 1]       = acc[mt][nt][1];
            o[(r0 + 8) * 32 + cc]     = acc[mt][nt][2];
            o[(r0 + 8) * 32 + cc + 1] = acc[mt][nt][3];
        }
}

// ---------------- reduce partials + temp + softmax over axis c ----------------
__global__ void softmax_kernel(const float* __restrict__ part, const float* __restrict__ temp,
                               float* __restrict__ attn) {
    int bh = blockIdx.x;
    int h = bh % HEADS;
    int d = threadIdx.x;
    float t = temp[h];
    float v[32];
#pragma unroll
    for (int c = 0; c < 32; c++) {
        float s = 0.f;
        for (int ch = 0; ch < 32; ch++)
            s += part[((size_t)bh * 32 + ch) * 1024 + c * 32 + d];
        v[c] = s * t;
    }
    float m = -1e30f;
#pragma unroll
    for (int c = 0; c < 32; c++) m = fmaxf(m, v[c]);
    float sum = 0.f;
#pragma unroll
    for (int c = 0; c < 32; c++) { v[c] = expf(v[c] - m); sum += v[c]; }
    float inv = 1.f / sum;
#pragma unroll
    for (int c = 0; c < 32; c++)
        attn[(size_t)bh * 1024 + c * 32 + d] = v[c] * inv;
}

// ---------------- fold attn into w_proj -> bf16 W2 ----------------
__global__ void w2_kernel(const float* __restrict__ attn, const float* __restrict__ wproj,
                          __nv_bfloat16* __restrict__ W2) {
    int bh = blockIdx.x;
    int b = bh / HEADS, h = bh % HEADS;
    __shared__ float sA[32][32];
    __shared__ float sW[32][192];
    int tid = threadIdx.x;          // 192
    for (int t = tid; t < 1024; t += 192)
        sA[t >> 5][t & 31] = attn[(size_t)bh * 1024 + t];
    for (int dd = 0; dd < 32; dd++)
        sW[dd][tid] = wproj[(h * HD + dd) * CDIM + tid];
    __syncthreads();
    int o = tid;
    for (int c = 0; c < 32; c++) {
        float acc = 0.f;
#pragma unroll
        for (int dd = 0; dd < 32; dd++) acc += sA[c][dd] * sW[dd][o];
        W2[((size_t)b * CDIM + h * HD + c) * CDIM + o] = __float2bfloat16(acc);
    }
}

// ---------------- launch ----------------
extern "C" void kernel_launch(void* const* d_in, const int* in_sizes, int n_in,
                              void* d_out, int out_size) {
    const float* x       = (const float*)d_in[0];
    const float* g1      = (const float*)d_in[1];
    const float* b1      = (const float*)d_in[2];
    const float* w_qkv   = (const float*)d_in[3];
    const float* w_qkv_dw= (const float*)d_in[4];
    const float* temp    = (const float*)d_in[5];
    const float* mean_q  = (const float*)d_in[6];
    const float* var_q   = (const float*)d_in[7];
    const float* mean_k  = (const float*)d_in[8];
    const float* var_k   = (const float*)d_in[9];
    const float* w_proj  = (const float*)d_in[10];
    const float* g2      = (const float*)d_in[11];
    const float* b2      = (const float*)d_in[12];
    const float* w_in    = (const float*)d_in[13];
    const float* w_ffn_dw= (const float*)d_in[14];
    const float* w_out   = (const float*)d_in[15];
    float* out = (float*)d_out;

    __nv_bfloat16 *p_y, *p_qkvp, *p_qkn, *p_v, *p_W2, *p_upre, *p_ug, *p_wqkv, *p_win, *p_wout;
    float *p_part, *p_attn, *p_x1;
    cudaGetSymbolAddress((void**)&p_y,    g_y);
    cudaGetSymbolAddress((void**)&p_qkvp, g_qkv_pre);
    cudaGetSymbolAddress((void**)&p_qkn,  g_qkn);
    cudaGetSymbolAddress((void**)&p_v,    g_v);
    cudaGetSymbolAddress((void**)&p_part, g_part);
    cudaGetSymbolAddress((void**)&p_attn, g_attn);
    cudaGetSymbolAddress((void**)&p_W2,   g_W2);
    cudaGetSymbolAddress((void**)&p_x1,   g_x1);
    cudaGetSymbolAddress((void**)&p_upre, g_upre);
    cudaGetSymbolAddress((void**)&p_ug,   g_ug);
    cudaGetSymbolAddress((void**)&p_wqkv, g_wqkv);
    cudaGetSymbolAddress((void**)&p_win,  g_win);
    cudaGetSymbolAddress((void**)&p_wout, g_wout);

    static bool attr_set = false;
    if (!attr_set) {
        cudaFuncSetAttribute(gemm_bf16_128, cudaFuncAttributeMaxDynamicSharedMemorySize,
                             (3 * ASZE + 3 * BSZ2) * 2);
        attr_set = true;
    }

    // 0. weight conversion (bf16, padded)
    cvt_pad<<<(CDIM * C3) / 256, 256>>>(w_qkv, CDIM, C3, p_wqkv, C3);
    cvt_pad<<<(CDIM * UPLD) / 256, 256>>>(w_in, CDIM, HID2, p_win, UPLD);
    cvt_pad_rows<<<(UGLD * CDIM) / 256, 256>>>(w_out, HID, CDIM, p_wout);

    // 1. LN1 -> bf16
    ln_kernel<<<NPIX / 8, 256>>>(x, g1, b1, p_y);
    // 2. qkv = y @ w_qkv -> bf16
    gemm_bf16<<<dim3(C3 / 64, NPIX / 128, 1), 256>>>(p_y, CDIM, p_wqkv, C3, 0, nullptr,
                                                     p_qkvp, 1, NPIX, CDIM, C3);
    // 3. dwconv 3x3 + q/k normalization (bf16 qkn) + v bf16
    dwconv_qkv<<<NPIX, 288>>>(p_qkvp, w_qkv_dw, mean_q, var_q, mean_k, var_k, p_qkn, p_v);
    // 4. K^T Q partials (tensor cores)
    attn_partial<<<dim3(4, HEADS, BATCH), 256>>>(p_qkn, p_part);
    // 5. softmax(axis=-2)
    softmax_kernel<<<48, 32>>>(p_part, temp, p_attn);
    // 6. fold attn into w_proj -> bf16 W2
    w2_kernel<<<48, 192>>>(p_attn, w_proj, p_W2);
    // 7. x1 = x + V @ W2[b]
    gemm_bf16<<<dim3(CDIM / 64, NPB / 128, BATCH), 256>>>(p_v, CDIM, p_W2, CDIM,
                                                          (long long)CDIM * CDIM, x,
                                                          p_x1, 0, NPB, CDIM, CDIM);
    // 8. LN2 -> bf16
    ln_kernel<<<NPIX / 8, 256>>>(p_x1, g2, b2, p_y);
    // 9. u_pre = y @ w_in (bf16 out, 128x128 tiles)
    gemm_bf16_128<<<dim3(UPLD / 128, NPIX / 128, 1), 256, (3 * ASZE + 3 * BSZ2) * 2>>>(
        p_y, CDIM, p_win, UPLD, p_upre, CDIM, UPLD);
    // 10. dwconv + GELU gate (bf162 vectorized)
    dwconv_ffn_gate<<<NPIX, 256>>>(p_upre, w_ffn_dw, p_ug);
    // 11. out = x1 + ug @ w_out (K=512 padded)
    gemm_bf16<<<dim3(CDIM / 64, NPIX / 128, 1), 256>>>(p_ug, UGLD, p_wout, CDIM, 0, p_x1,
                                                       out, 0, NPIX, UGLD, CDIM);
    (void)in_sizes; (void)n_in; (void)out_size;
}

// round 16
// speedup vs baseline: 1.9340x; 1.0894x over previous
#include <cuda_runtime.h>
#include <cuda_bf16.h>
#include <math.h>

#define NPIX   131072
#define BATCH  8
#define HH     128
#define WW     128
#define CDIM   192
#define C3     576
#define QPLD   640        // padded M for qkv GEMM output (576 -> 640)
#define HEADS  6
#define HD     32
#define HID    510
#define HID2   1020
#define UPLD   1024       // padded M for FFN-in GEMM output
#define UGLD   512        // padded lda for gated ffn activation
#define NPB    16384

// ---------------- scratch (device globals) ----------------
__device__ __align__(128) __nv_bfloat16 g_y[(size_t)NPIX * CDIM];
__device__ __align__(128) __nv_bfloat16 g_qkv_pre[(size_t)NPIX * QPLD];
__device__ __align__(128) __nv_bfloat16 g_qkn[(size_t)NPIX * 384];   // normalized q,k (bf16)
__device__ __align__(128) __nv_bfloat16 g_v[(size_t)NPIX * CDIM];
__device__ __align__(128) float g_part[48 * 32 * 1024];
__device__ __align__(128) float g_attn[48 * 1024];
__device__ __align__(128) __nv_bfloat16 g_W2[BATCH * CDIM * CDIM];
__device__ __align__(128) float g_x1[(size_t)NPIX * CDIM];
__device__ __align__(128) __nv_bfloat16 g_upre[(size_t)NPIX * UPLD];
__device__ __align__(128) __nv_bfloat16 g_ug[(size_t)NPIX * UGLD];
// bf16 weights (padded)
__device__ __align__(128) __nv_bfloat16 g_wqkv[CDIM * QPLD];    // cols 576..639 zero
__device__ __align__(128) __nv_bfloat16 g_win[CDIM * UPLD];     // cols 1020..1023 zero
__device__ __align__(128) __nv_bfloat16 g_wout[UGLD * CDIM];    // rows 510,511 zero

// ---------------- asm helpers ----------------
__device__ __forceinline__ void ldsm4(unsigned* r, unsigned addr) {
    asm volatile("ldmatrix.sync.aligned.m8n8.x4.shared.b16 {%0,%1,%2,%3}, [%4];"
                 : "=r"(r[0]), "=r"(r[1]), "=r"(r[2]), "=r"(r[3]) : "r"(addr));
}
__device__ __forceinline__ void ldsm4t(unsigned* r, unsigned addr) {
    asm volatile("ldmatrix.sync.aligned.m8n8.x4.trans.shared.b16 {%0,%1,%2,%3}, [%4];"
                 : "=r"(r[0]), "=r"(r[1]), "=r"(r[2]), "=r"(r[3]) : "r"(addr));
}
__device__ __forceinline__ void mma_bf16(float* d, const unsigned* a, unsigned b0, unsigned b1) {
    asm volatile(
        "mma.sync.aligned.m16n8k16.row.col.f32.bf16.bf16.f32 "
        "{%0,%1,%2,%3},{%4,%5,%6,%7},{%8,%9},{%0,%1,%2,%3};"
        : "+f"(d[0]), "+f"(d[1]), "+f"(d[2]), "+f"(d[3])
        : "r"(a[0]), "r"(a[1]), "r"(a[2]), "r"(a[3]), "r"(b0), "r"(b1));
}
__device__ __forceinline__ void cp16(unsigned dst, const void* src) {
    asm volatile("cp.async.cg.shared.global [%0], [%1], 16;" :: "r"(dst), "l"(src));
}
__device__ __forceinline__ void cp_commit() { asm volatile("cp.async.commit_group;"); }
__device__ __forceinline__ void cp_wait1() { asm volatile("cp.async.wait_group 1;"); }
__device__ __forceinline__ void cp_wait0() { asm volatile("cp.async.wait_group 0;"); }

// ---------------- weight convert + pad ----------------
__global__ void cvt_pad(const float* __restrict__ src, int srows, int scols,
                        __nv_bfloat16* __restrict__ dst, int dcols) {
    size_t i = (size_t)blockIdx.x * 256 + threadIdx.x;
    int r = (int)(i / dcols), cc = (int)(i % dcols);
    float v = (cc < scols) ? src[(size_t)r * scols + cc] : 0.f;
    dst[i] = __float2bfloat16(v);
}
__global__ void cvt_pad_rows(const float* __restrict__ src, int srows, int cols,
                             __nv_bfloat16* __restrict__ dst) {
    size_t i = (size_t)blockIdx.x * 256 + threadIdx.x;
    int r = (int)(i / cols), cc = (int)(i % cols);
    float v = (r < srows) ? src[(size_t)r * cols + cc] : 0.f;
    dst[i] = __float2bfloat16(v);
}

// ---------------- LayerNorm -> bf16 output ----------------
__global__ void ln_kernel(const float* __restrict__ x, const float* __restrict__ g,
                          const float* __restrict__ b, __nv_bfloat16* __restrict__ y) {
    size_t warp = ((size_t)blockIdx.x * blockDim.x + threadIdx.x) >> 5;
    int lane = threadIdx.x & 31;
    const float* xr = x + warp * CDIM;
    float v[6]; float s = 0.f, s2 = 0.f;
#pragma unroll
    for (int i = 0; i < 6; i++) { v[i] = xr[lane + 32 * i]; s += v[i]; s2 += v[i] * v[i]; }
#pragma unroll
    for (int o = 16; o; o >>= 1) {
        s  += __shfl_xor_sync(0xffffffffu, s, o);
        s2 += __shfl_xor_sync(0xffffffffu, s2, o);
    }
    float mu  = s * (1.f / CDIM);
    float var = s2 * (1.f / CDIM) - mu * mu;
    float rs = rsqrtf(var + 1e-3f);
    __nv_bfloat16* yr = y + warp * CDIM;
#pragma unroll
    for (int i = 0; i < 6; i++) {
        int c = lane + 32 * i;
        yr[c] = __float2bfloat16((v[i] - mu) * rs * g[c] + b[c]);
    }
}

// ---------------- bf16 GEMM 128x64 tile, cp.async 3-stage: C = A*B (+R) ----------------
#define LDAK 40
#define LDBN 72
#define ASZE (128 * LDAK)
#define BSZE (32 * LDBN)
__global__ void __launch_bounds__(256) gemm_bf16(
    const __nv_bfloat16* __restrict__ A, int lda,
    const __nv_bfloat16* __restrict__ B, int ldb, long long bstride,
    const float* __restrict__ R,
    void* __restrict__ Cout, int obf16,
    int Nper, int K, int M)
{
    __shared__ __nv_bfloat16 As[3 * ASZE];
    __shared__ __nv_bfloat16 Bs[3 * BSZE];

    int bz = blockIdx.z;
    A += (size_t)bz * Nper * lda;
    B += (size_t)bz * bstride;
    size_t cbase = (size_t)bz * Nper * M;
    if (R) R += cbase;

    int tid = threadIdx.x;
    int row0 = blockIdx.y * 128;
    int col0 = blockIdx.x * 64;
    int warp = tid >> 5, lane = tid & 31;
    int wm = warp & 3, wn = warp >> 2;
    int g = lane >> 2, tig = lane & 3;
    int lrow = lane & 15, lhi = lane >> 4;

    unsigned as_u = (unsigned)__cvta_generic_to_shared(As);
    unsigned bs_u = (unsigned)__cvta_generic_to_shared(Bs);

    int ar0 = tid >> 2, ak0 = (tid & 3) << 3;
    int ar1 = (tid + 256) >> 2, ak1 = ((tid + 256) & 3) << 3;
    int bkr = tid >> 3, bnc = (tid & 7) << 3;

    float acc[2][4][4];
#pragma unroll
    for (int mt = 0; mt < 2; mt++)
#pragma unroll
        for (int nt = 0; nt < 4; nt++)
#pragma unroll
            for (int i = 0; i < 4; i++) acc[mt][nt][i] = 0.f;

    auto issue = [&](int s, int k0) {
        unsigned ab = as_u + s * (ASZE * 2);
        unsigned bb = bs_u + s * (BSZE * 2);
        cp16(ab + (ar0 * LDAK + ak0) * 2, A + (size_t)(row0 + ar0) * lda + k0 + ak0);
        cp16(ab + (ar1 * LDAK + ak1) * 2, A + (size_t)(row0 + ar1) * lda + k0 + ak1);
        cp16(bb + (bkr * LDBN + bnc) * 2, B + (size_t)(k0 + bkr) * ldb + col0 + bnc);
        cp_commit();
    };
    auto compute = [&](int s) {
        unsigned ab = as_u + s * (ASZE * 2);
        unsigned bb = bs_u + s * (BSZE * 2);
#pragma unroll
        for (int ks = 0; ks < 2; ks++) {
            unsigned afr[2][4];
#pragma unroll
            for (int mt = 0; mt < 2; mt++)
                ldsm4(afr[mt], ab + ((wm * 32 + mt * 16 + lrow) * LDAK + ks * 16 + lhi * 8) * 2);
            unsigned bfr[2][4];
#pragma unroll
            for (int np = 0; np < 2; np++)
                ldsm4t(bfr[np], bb + ((ks * 16 + lrow) * LDBN + wn * 32 + np * 16 + lhi * 8) * 2);
#pragma unroll
            for (int mt = 0; mt < 2; mt++)
#pragma unroll
                for (int np = 0; np < 2; np++) {
                    mma_bf16(acc[mt][np * 2 + 0], afr[mt], bfr[np][0], bfr[np][1]);
                    mma_bf16(acc[mt][np * 2 + 1], afr[mt], bfr[np][2], bfr[np][3]);
                }
        }
    };

    int kt = K >> 5;
    issue(0, 0);
    issue(1, 32);
    for (int it = 0; it < kt; it++) {
        if (it + 2 < kt) cp_wait1(); else cp_wait0();
        __syncthreads();
        if (it + 2 < kt) issue((it + 2) % 3, (it + 2) * 32);
        compute(it % 3);
    }

#pragma unroll
    for (int mt = 0; mt < 2; mt++) {
        size_t r = (size_t)row0 + wm * 32 + mt * 16 + g;
#pragma unroll
        for (int nt = 0; nt < 4; nt++) {
            int col = col0 + wn * 32 + nt * 8 + tig * 2;
            if (obf16) {
                __nv_bfloat16* C = (__nv_bfloat16*)Cout + cbase;
                *reinterpret_cast<__nv_bfloat162*>(C + r * M + col) =
                    __floats2bfloat162_rn(acc[mt][nt][0], acc[mt][nt][1]);
                *reinterpret_cast<__nv_bfloat162*>(C + (r + 8) * M + col) =
                    __floats2bfloat162_rn(acc[mt][nt][2], acc[mt][nt][3]);
            } else {
                float* C = (float*)Cout + cbase;
                float2 o0 = make_float2(acc[mt][nt][0], acc[mt][nt][1]);
                float2 o1 = make_float2(acc[mt][nt][2], acc[mt][nt][3]);
                if (R) {
                    float2 r0 = *reinterpret_cast<const float2*>(R + r * M + col);
                    float2 r1 = *reinterpret_cast<const float2*>(R + (r + 8) * M + col);
                    o0.x += r0.x; o0.y += r0.y; o1.x += r1.x; o1.y += r1.y;
                }
                *reinterpret_cast<float2*>(C + r * M + col) = o0;
                *reinterpret_cast<float2*>(C + (r + 8) * M + col) = o1;
            }
        }
    }
}

// ---------------- bf16 GEMM 128x128 tile (dynamic smem), bf16 output ----------------
#define LDB2 136
#define BSZ2 (32 * LDB2)
__global__ void __launch_bounds__(256) gemm_bf16_128(
    const __nv_bfloat16* __restrict__ A, int lda,
    const __nv_bfloat16* __restrict__ B, int ldb,
    __nv_bfloat16* __restrict__ C,
    int K, int M)
{
    extern __shared__ __nv_bfloat16 smem[];
    __nv_bfloat16* As = smem;
    __nv_bfloat16* Bs = smem + 3 * ASZE;

    int tid = threadIdx.x;
    int row0 = blockIdx.y * 128;
    int col0 = blockIdx.x * 128;
    int warp = tid >> 5, lane = tid & 31;
    int wm = warp & 3, wn = warp >> 2;
    int g = lane >> 2, tig = lane & 3;
    int lrow = lane & 15, lhi = lane >> 4;

    unsigned as_u = (unsigned)__cvta_generic_to_shared(As);
    unsigned bs_u = (unsigned)__cvta_generic_to_shared(Bs);

    int ar0 = tid >> 2, ak0 = (tid & 3) << 3;
    int ar1 = (tid + 256) >> 2, ak1 = ((tid + 256) & 3) << 3;
    int bkr0 = tid >> 4, bnc0 = (tid & 15) << 3;
    int bkr1 = (tid + 256) >> 4, bnc1 = ((tid + 256) & 15) << 3;

    float acc[2][8][4];
#pragma unroll
    for (int mt = 0; mt < 2; mt++)
#pragma unroll
        for (int nt = 0; nt < 8; nt++)
#pragma unroll
            for (int i = 0; i < 4; i++) acc[mt][nt][i] = 0.f;

    auto issue = [&](int s, int k0) {
        unsigned ab = as_u + s * (ASZE * 2);
        unsigned bb = bs_u + s * (BSZ2 * 2);
        cp16(ab + (ar0 * LDAK + ak0) * 2, A + (size_t)(row0 + ar0) * lda + k0 + ak0);
        cp16(ab + (ar1 * LDAK + ak1) * 2, A + (size_t)(row0 + ar1) * lda + k0 + ak1);
        cp16(bb + (bkr0 * LDB2 + bnc0) * 2, B + (size_t)(k0 + bkr0) * ldb + col0 + bnc0);
        cp16(bb + (bkr1 * LDB2 + bnc1) * 2, B + (size_t)(k0 + bkr1) * ldb + col0 + bnc1);
        cp_commit();
    };
    auto compute = [&](int s) {
        unsigned ab = as_u + s * (ASZE * 2);
        unsigned bb = bs_u + s * (BSZ2 * 2);
#pragma unroll
        for (int ks = 0; ks < 2; ks++) {
            unsigned afr[2][4];
#pragma unroll
            for (int mt = 0; mt < 2; mt++)
                ldsm4(afr[mt], ab + ((wm * 32 + mt * 16 + lrow) * LDAK + ks * 16 + lhi * 8) * 2);
            unsigned bfr[4][4];
#pragma unroll
            for (int np = 0; np < 4; np++)
                ldsm4t(bfr[np], bb + ((ks * 16 + lrow) * LDB2 + wn * 64 + np * 16 + lhi * 8) * 2);
#pragma unroll
            for (int mt = 0; mt < 2; mt++)
#pragma unroll
                for (int np = 0; np < 4; np++) {
                    mma_bf16(acc[mt][np * 2 + 0], afr[mt], bfr[np][0], bfr[np][1]);
                    mma_bf16(acc[mt][np * 2 + 1], afr[mt], bfr[np][2], bfr[np][3]);
                }
        }
    };

    int kt = K >> 5;
    issue(0, 0);
    issue(1, 32);
    for (int it = 0; it < kt; it++) {
        if (it + 2 < kt) cp_wait1(); else cp_wait0();
        __syncthreads();
        if (it + 2 < kt) issue((it + 2) % 3, (it + 2) * 32);
        compute(it % 3);
    }

#pragma unroll
    for (int mt = 0; mt < 2; mt++) {
        size_t r = (size_t)row0 + wm * 32 + mt * 16 + g;
#pragma unroll
        for (int nt = 0; nt < 8; nt++) {
            int col = col0 + wn * 64 + nt * 8 + tig * 2;
            *reinterpret_cast<__nv_bfloat162*>(C + r * M + col) =
                __floats2bfloat162_rn(acc[mt][nt][0], acc[mt][nt][1]);
            *reinterpret_cast<__nv_bfloat162*>(C + (r + 8) * M + col) =
                __floats2bfloat162_rn(acc[mt][nt][2], acc[mt][nt][3]);
        }
    }
}

// ---------------- qkv dwconv: sliding-window, 8 pixels per block ----------------
// grid 16384 blocks (8 batches x 128 rows x 16 segments), 288 threads (channel pairs).
__global__ void __launch_bounds__(288) dwconv_qkv(
        const __nv_bfloat16* __restrict__ in, const float* __restrict__ w,
        const float* __restrict__ mq, const float* __restrict__ vq,
        const float* __restrict__ mk, const float* __restrict__ vk,
        __nv_bfloat16* __restrict__ qkn, __nv_bfloat16* __restrict__ v) {
    int bid = blockIdx.x;
    int seg = bid & 15, row = bid >> 4;
    int b = row >> 7, yy = row & 127;
    int x0 = seg << 3;
    int c2 = threadIdx.x;
    int c = c2 * 2;

    float2 wv[9];
#pragma unroll
    for (int t = 0; t < 9; t++)
        wv[t] = *reinterpret_cast<const float2*>(w + t * C3 + c);

    bool yv[3]; size_t rb[3];
#pragma unroll
    for (int r = 0; r < 3; r++) {
        int yn = yy - 1 + r;
        yv[r] = (unsigned)yn < HH;
        rb[r] = ((size_t)(b << 14) + (size_t)(yn << 7)) * QPLD + c;
    }

    float2 cA[3], cB[3], cC[3];
    auto ldcol = [&](int x, float2* dst) {
        bool xv = (unsigned)x < WW;
#pragma unroll
        for (int r = 0; r < 3; r++) {
            if (xv && yv[r]) {
                __nv_bfloat162 a = *reinterpret_cast<const __nv_bfloat162*>(
                    in + rb[r] + (size_t)x * QPLD);
                dst[r] = make_float2(__low2float(a), __high2float(a));
            } else dst[r] = make_float2(0.f, 0.f);
        }
    };
    ldcol(x0 - 1, cA);
    ldcol(x0, cB);

#pragma unroll
    for (int dx = 0; dx < 8; dx++) {
        int x = x0 + dx;
        ldcol(x + 1, cC);
        float a0 = 0.f, a1 = 0.f;
#pragma unroll
        for (int r = 0; r < 3; r++) {
            a0 += cA[r].x * wv[r * 3 + 0].x; a1 += cA[r].y * wv[r * 3 + 0].y;
            a0 += cB[r].x * wv[r * 3 + 1].x; a1 += cB[r].y * wv[r * 3 + 1].y;
            a0 += cC[r].x * wv[r * 3 + 2].x; a1 += cC[r].y * wv[r * 3 + 2].y;
        }
        int hw = (yy << 7) + x;
        size_t p = (size_t)(b << 14) + hw;
        if (c2 < 96) {
            float m = mq[hw], rs = rsqrtf(vq[hw]);
            reinterpret_cast<__nv_bfloat162*>(qkn + p * 384)[c2] =
                __floats2bfloat162_rn((a0 - m) * rs, (a1 - m) * rs);
        } else if (c2 < 192) {
            float m = mk[hw], rs = rsqrtf(vk[hw]);
            reinterpret_cast<__nv_bfloat162*>(qkn + p * 384)[c2] =
                __floats2bfloat162_rn((a0 - m) * rs, (a1 - m) * rs);
        } else {
            reinterpret_cast<__nv_bfloat162*>(v + p * CDIM)[c2 - 192] =
                __floats2bfloat162_rn(a0, a1);
        }
#pragma unroll
        for (int r = 0; r < 3; r++) { cA[r] = cB[r]; cB[r] = cC[r]; }
    }
}

// ---------------- FFN dwconv + GELU gate: sliding-window, 8 pixels per block ----------
__global__ void __launch_bounds__(256) dwconv_ffn_gate(
        const __nv_bfloat16* __restrict__ in, const float* __restrict__ w,
        __nv_bfloat16* __restrict__ out) {
    int bid = blockIdx.x;
    int seg = bid & 15, row = bid >> 4;
    int b = row >> 7, yy = row & 127;
    int x0 = seg << 3;
    int i = threadIdx.x;
    size_t outbase = ((size_t)(b << 14) + (size_t)(yy << 7) + x0) * UGLD;
    if (i >= 255) {
#pragma unroll
        for (int dx = 0; dx < 8; dx++)
            *reinterpret_cast<__nv_bfloat162*>(out + outbase + dx * UGLD + 510) =
                __floats2bfloat162_rn(0.f, 0.f);
        return;
    }
    int c = i * 2;

    float2 w1[9], w2[9];
#pragma unroll
    for (int t = 0; t < 9; t++) {
        w1[t] = *reinterpret_cast<const float2*>(w + t * HID2 + c);
        w2[t] = *reinterpret_cast<const float2*>(w + t * HID2 + HID + c);
    }

    bool yv[3]; size_t rb[3];
#pragma unroll
    for (int r = 0; r < 3; r++) {
        int yn = yy - 1 + r;
        yv[r] = (unsigned)yn < HH;
        rb[r] = ((size_t)(b << 14) + (size_t)(yn << 7)) * UPLD + c;
    }

    float2 cA1[3], cB1[3], cC1[3], cA2[3], cB2[3], cC2[3];
    auto ldcol = [&](int x, float2* d1, float2* d2) {
        bool xv = (unsigned)x < WW;
#pragma unroll
        for (int r = 0; r < 3; r++) {
            if (xv && yv[r]) {
                size_t base = rb[r] + (size_t)x * UPLD;
                __nv_bfloat162 a = *reinterpret_cast<const __nv_bfloat162*>(in + base);
                __nv_bfloat162 bb = *reinterpret_cast<const __nv_bfloat162*>(in + base + HID);
                d1[r] = make_float2(__low2float(a), __high2float(a));
                d2[r] = make_float2(__low2float(bb), __high2float(bb));
            } else {
                d1[r] = make_float2(0.f, 0.f);
                d2[r] = make_float2(0.f, 0.f);
            }
        }
    };
    ldcol(x0 - 1, cA1, cA2);
    ldcol(x0, cB1, cB2);

#pragma unroll
    for (int dx = 0; dx < 8; dx++) {
        ldcol(x0 + dx + 1, cC1, cC2);
        float a10 = 0.f, a11 = 0.f, a20 = 0.f, a21 = 0.f;
#pragma unroll
        for (int r = 0; r < 3; r++) {
            a10 += cA1[r].x * w1[r * 3 + 0].x; a11 += cA1[r].y * w1[r * 3 + 0].y;
            a10 += cB1[r].x * w1[r * 3 + 1].x; a11 += cB1[r].y * w1[r * 3 + 1].y;
            a10 += cC1[r].x * w1[r * 3 + 2].x; a11 += cC1[r].y * w1[r * 3 + 2].y;
            a20 += cA2[r].x * w2[r * 3 + 0].x; a21 += cA2[r].y * w2[r * 3 + 0].y;
            a20 += cB2[r].x * w2[r * 3 + 1].x; a21 += cB2[r].y * w2[r * 3 + 1].y;
            a20 += cC2[r].x * w2[r * 3 + 2].x; a21 += cC2[r].y * w2[r * 3 + 2].y;
        }
        float gl0 = 0.5f * a10 * (1.f + erff(a10 * 0.70710678118654752f));
        float gl1 = 0.5f * a11 * (1.f + erff(a11 * 0.70710678118654752f));
        reinterpret_cast<__nv_bfloat162*>(out + outbase + dx * UGLD)[i] =
            __floats2bfloat162_rn(gl0 * a20, gl1 * a21);
#pragma unroll
        for (int r = 0; r < 3; r++) {
            cA1[r] = cB1[r]; cB1[r] = cC1[r];
            cA2[r] = cB2[r]; cB2[r] = cC2[r];
        }
    }
}

// ---------------- attention K^T Q partials via tensor cores ----------------
#define LDQ 40
#define LDKT 24
__global__ void __launch_bounds__(256) attn_partial(
        const __nv_bfloat16* __restrict__ qkn, float* __restrict__ part) {
    int chunk = blockIdx.x, h = blockIdx.y, b = blockIdx.z;
    __shared__ __nv_bfloat16 sq[8][16 * LDQ];
    __shared__ __nv_bfloat16 skt[8][32 * LDKT];
    int tid = threadIdx.x, warp = tid >> 5, lane = tid & 31;
    int lrow = lane & 15, lhi = lane >> 4;
    size_t rowbase = ((size_t)b * NPB + chunk * 4096 + warp * 512) * 384 + h * HD;
    unsigned squ = (unsigned)__cvta_generic_to_shared(sq[warp]);
    unsigned sktu = (unsigned)__cvta_generic_to_shared(skt[warp]);

    float acc[2][4][4];
#pragma unroll
    for (int mt = 0; mt < 2; mt++)
#pragma unroll
        for (int nt = 0; nt < 4; nt++)
#pragma unroll
            for (int i = 0; i < 4; i++) acc[mt][nt][i] = 0.f;

    for (int st = 0; st < 32; st++) {
#pragma unroll
        for (int i = 0; i < 8; i++) {
            int cch = lane + i * 32;
            int row = cch >> 4, prt = cch & 15;
            const __nv_bfloat16* src = qkn + rowbase + (size_t)(st * 16 + row) * 384 +
                                       ((prt & 8) ? (192 + (prt - 8) * 4) : prt * 4);
            uint2 raw = *reinterpret_cast<const uint2*>(src);
            if (prt < 8) {
                *reinterpret_cast<uint2*>(&sq[warp][row * LDQ + prt * 4]) = raw;
            } else {
                const __nv_bfloat16* pv = reinterpret_cast<const __nv_bfloat16*>(&raw);
                int c4 = (prt - 8) * 4;
                skt[warp][(c4 + 0) * LDKT + row] = pv[0];
                skt[warp][(c4 + 1) * LDKT + row] = pv[1];
                skt[warp][(c4 + 2) * LDKT + row] = pv[2];
                skt[warp][(c4 + 3) * LDKT + row] = pv[3];
            }
        }
        __syncwarp();
        unsigned afr[2][4], bfr[2][4];
#pragma unroll
        for (int mt = 0; mt < 2; mt++)
            ldsm4(afr[mt], sktu + ((mt * 16 + lrow) * LDKT + lhi * 8) * 2);
#pragma unroll
        for (int np = 0; np < 2; np++)
            ldsm4t(bfr[np], squ + (lrow * LDQ + np * 16 + lhi * 8) * 2);
#pragma unroll
        for (int mt = 0; mt < 2; mt++)
#pragma unroll
            for (int np = 0; np < 2; np++) {
                mma_bf16(acc[mt][np * 2 + 0], afr[mt], bfr[np][0], bfr[np][1]);
                mma_bf16(acc[mt][np * 2 + 1], afr[mt], bfr[np][2], bfr[np][3]);
            }
        __syncwarp();
    }
    int g = lane >> 2, tig = lane & 3;
    float* o = part + ((size_t)(b * HEADS + h) * 32 + chunk * 8 + warp) * 1024;
#pragma unroll
    for (int mt = 0; mt < 2; mt++)
#pragma unroll
        for (int nt = 0; nt < 4; nt++) {
            int r0 = mt * 16 + g, cc = nt * 8 + tig * 2;
            o[r0 * 32 + cc]           = acc[mt][nt][0];
            o[r0 * 32 + cc + 1]       = acc[mt][nt][1];
            o[(r0 + 8) * 32 + cc]     = acc[mt][nt][2];
            o[(r0 + 8) * 32 + cc + 1] = acc[mt][nt][3];
        }
}

// ---------------- reduce partials + temp + softmax over axis c ----------------
__global__ void softmax_kernel(const float* __restrict__ part, const float* __restrict__ temp,
                               float* __restrict__ attn) {
    int bh = blockIdx.x;
    int h = bh % HEADS;
    int d = threadIdx.x;
    float t = temp[h];
    float v[32];
#pragma unroll
    for (int c = 0; c < 32; c++) {
        float s = 0.f;
        for (int ch = 0; ch < 32; ch++)
            s += part[((size_t)bh * 32 + ch) * 1024 + c * 32 + d];
        v[c] = s * t;
    }
    float m = -1e30f;
#pragma unroll
    for (int c = 0; c < 32; c++) m = fmaxf(m, v[c]);
    float sum = 0.f;
#pragma unroll
    for (int c = 0; c < 32; c++) { v[c] = expf(v[c] - m); sum += v[c]; }
    float inv = 1.f / sum;
#pragma unroll
    for (int c = 0; c < 32; c++)
        attn[(size_t)bh * 1024 + c * 32 + d] = v[c] * inv;
}

// ---------------- fold attn into w_proj -> bf16 W2 ----------------
__global__ void w2_kernel(const float* __restrict__ attn, const float* __restrict__ wproj,
                          __nv_bfloat16* __restrict__ W2) {
    int bh = blockIdx.x;
    int b = bh / HEADS, h = bh % HEADS;
    __shared__ float sA[32][32];
    __shared__ float sW[32][192];
    int tid = threadIdx.x;          // 192
    for (int t = tid; t < 1024; t += 192)
        sA[t >> 5][t & 31] = attn[(size_t)bh * 1024 + t];
    for (int dd = 0; dd < 32; dd++)
        sW[dd][tid] = wproj[(h * HD + dd) * CDIM + tid];
    __syncthreads();
    int o = tid;
    for (int c = 0; c < 32; c++) {
        float acc = 0.f;
#pragma unroll
        for (int dd = 0; dd < 32; dd++) acc += sA[c][dd] * sW[dd][o];
        W2[((size_t)b * CDIM + h * HD + c) * CDIM + o] = __float2bfloat16(acc);
    }
}

// ---------------- launch ----------------
extern "C" void kernel_launch(void* const* d_in, const int* in_sizes, int n_in,
                              void* d_out, int out_size) {
    const float* x       = (const float*)d_in[0];
    const float* g1      = (const float*)d_in[1];
    const float* b1      = (const float*)d_in[2];
    const float* w_qkv   = (const float*)d_in[3];
    const float* w_qkv_dw= (const float*)d_in[4];
    const float* temp    = (const float*)d_in[5];
    const float* mean_q  = (const float*)d_in[6];
    const float* var_q   = (const float*)d_in[7];
    const float* mean_k  = (const float*)d_in[8];
    const float* var_k   = (const float*)d_in[9];
    const float* w_proj  = (const float*)d_in[10];
    const float* g2      = (const float*)d_in[11];
    const float* b2      = (const float*)d_in[12];
    const float* w_in    = (const float*)d_in[13];
    const float* w_ffn_dw= (const float*)d_in[14];
    const float* w_out   = (const float*)d_in[15];
    float* out = (float*)d_out;

    __nv_bfloat16 *p_y, *p_qkvp, *p_qkn, *p_v, *p_W2, *p_upre, *p_ug, *p_wqkv, *p_win, *p_wout;
    float *p_part, *p_attn, *p_x1;
    cudaGetSymbolAddress((void**)&p_y,    g_y);
    cudaGetSymbolAddress((void**)&p_qkvp, g_qkv_pre);
    cudaGetSymbolAddress((void**)&p_qkn,  g_qkn);
    cudaGetSymbolAddress((void**)&p_v,    g_v);
    cudaGetSymbolAddress((void**)&p_part, g_part);
    cudaGetSymbolAddress((void**)&p_attn, g_attn);
    cudaGetSymbolAddress((void**)&p_W2,   g_W2);
    cudaGetSymbolAddress((void**)&p_x1,   g_x1);
    cudaGetSymbolAddress((void**)&p_upre, g_upre);
    cudaGetSymbolAddress((void**)&p_ug,   g_ug);
    cudaGetSymbolAddress((void**)&p_wqkv, g_wqkv);
    cudaGetSymbolAddress((void**)&p_win,  g_win);
    cudaGetSymbolAddress((void**)&p_wout, g_wout);

    static bool attr_set = false;
    if (!attr_set) {
        cudaFuncSetAttribute(gemm_bf16_128, cudaFuncAttributeMaxDynamicSharedMemorySize,
                             (3 * ASZE + 3 * BSZ2) * 2);
        attr_set = true;
    }
    const int smem128 = (3 * ASZE + 3 * BSZ2) * 2;

    // 0. weight conversion (bf16, padded)
    cvt_pad<<<(CDIM * QPLD) / 256, 256>>>(w_qkv, CDIM, C3, p_wqkv, QPLD);
    cvt_pad<<<(CDIM * UPLD) / 256, 256>>>(w_in, CDIM, HID2, p_win, UPLD);
    cvt_pad_rows<<<(UGLD * CDIM) / 256, 256>>>(w_out, HID, CDIM, p_wout);

    // 1. LN1 -> bf16
    ln_kernel<<<NPIX / 8, 256>>>(x, g1, b1, p_y);
    // 2. qkv = y @ w_qkv -> bf16 (M padded to 640, 128x128 tiles)
    gemm_bf16_128<<<dim3(QPLD / 128, NPIX / 128, 1), 256, smem128>>>(
        p_y, CDIM, p_wqkv, QPLD, p_qkvp, CDIM, QPLD);
    // 3. dwconv 3x3 + q/k normalization (sliding window, 8 px/block)
    dwconv_qkv<<<NPIX / 8, 288>>>(p_qkvp, w_qkv_dw, mean_q, var_q, mean_k, var_k, p_qkn, p_v);
    // 4. K^T Q partials (tensor cores)
    attn_partial<<<dim3(4, HEADS, BATCH), 256>>>(p_qkn, p_part);
    // 5. softmax(axis=-2)
    softmax_kernel<<<48, 32>>>(p_part, temp, p_attn);
    // 6. fold attn into w_proj -> bf16 W2
    w2_kernel<<<48, 192>>>(p_attn, w_proj, p_W2);
    // 7. x1 = x + V @ W2[b]
    gemm_bf16<<<dim3(CDIM / 64, NPB / 128, BATCH), 256>>>(p_v, CDIM, p_W2, CDIM,
                                                          (long long)CDIM * CDIM, x,
                                                          p_x1, 0, NPB, CDIM, CDIM);
    // 8. LN2 -> bf16
    ln_kernel<<<NPIX / 8, 256>>>(p_x1, g2, b2, p_y);
    // 9. u_pre = y @ w_in (bf16 out, 128x128 tiles)
    gemm_bf16_128<<<dim3(UPLD / 128, NPIX / 128, 1), 256, smem128>>>(
        p_y, CDIM, p_win, UPLD, p_upre, CDIM, UPLD);
    // 10. dwconv + GELU gate (sliding window, 8 px/block)
    dwconv_ffn_gate<<<NPIX / 8, 256>>>(p_upre, w_ffn_dw, p_ug);
    // 11. out = x1 + ug @ w_out (K=512 padded)
    gemm_bf16<<<dim3(CDIM / 64, NPIX / 128, 1), 256>>>(p_ug, UGLD, p_wout, CDIM, 0, p_x1,
                                                       out, 0, NPIX, UGLD, CDIM);
    (void)in_sizes; (void)n_in; (void)out_size;
}